// round 4
// baseline (speedup 1.0000x reference)
#include <cuda_runtime.h>
#include <cstddef>

#define Bz   4
#define Ssz  1024
#define Pz   1024
#define Ez   1024
#define Hz   16
#define Dz   64
#define NSz  2048          // P + S
#define Mz   4096          // B*S
#define E3   3072

// Scratch (no cudaMalloc allowed)
__device__ __align__(16) float g_qkv[(size_t)Mz * E3];    // [4096, 3072]
__device__ __align__(16) float g_attn[(size_t)Mz * Ez];   // [4096, 1024]

// ---------------------------------------------------------------------------
// SGEMM: C[M,N] = A[M,K] @ B[K,N] + bias[N].  BM=BN=128, BK=8, 256 thr, 8x8.
// ---------------------------------------------------------------------------
__global__ __launch_bounds__(256) void sgemm_bias(
    const float* __restrict__ A, const float* __restrict__ B,
    const float* __restrict__ bias, float* __restrict__ C,
    int M, int N, int K)
{
    __shared__ __align__(16) float As[8][128];
    __shared__ __align__(16) float Bs[8][128];

    const int bx = blockIdx.x;   // N tiles
    const int by = blockIdx.y;   // M tiles
    const int tid = threadIdx.x;

    const int a_row = tid >> 1;          // 0..127
    const int a_col = (tid & 1) * 4;     // 0 or 4
    const int b_row = tid >> 5;          // 0..7
    const int b_col = (tid & 31) * 4;    // 0..124

    const float* Ab = A + (size_t)(by * 128) * K;
    const float* Bb = B + (size_t)bx * 128;

    float acc[8][8];
#pragma unroll
    for (int i = 0; i < 8; i++)
#pragma unroll
        for (int j = 0; j < 8; j++) acc[i][j] = 0.f;

    const int tx = tid & 15, ty = tid >> 4;

    for (int k0 = 0; k0 < K; k0 += 8) {
        float4 av = *(const float4*)(Ab + (size_t)a_row * K + k0 + a_col);
        As[a_col + 0][a_row] = av.x;
        As[a_col + 1][a_row] = av.y;
        As[a_col + 2][a_row] = av.z;
        As[a_col + 3][a_row] = av.w;
        float4 bv = *(const float4*)(Bb + (size_t)(k0 + b_row) * N + b_col);
        *(float4*)&Bs[b_row][b_col] = bv;
        __syncthreads();

#pragma unroll
        for (int k = 0; k < 8; k++) {
            float ar[8], br[8];
            *(float4*)&ar[0] = *(const float4*)&As[k][ty * 4];
            *(float4*)&ar[4] = *(const float4*)&As[k][64 + ty * 4];
            *(float4*)&br[0] = *(const float4*)&Bs[k][tx * 4];
            *(float4*)&br[4] = *(const float4*)&Bs[k][64 + tx * 4];
#pragma unroll
            for (int i = 0; i < 8; i++)
#pragma unroll
                for (int j = 0; j < 8; j++)
                    acc[i][j] += ar[i] * br[j];
        }
        __syncthreads();
    }

    float* Cb = C + (size_t)(by * 128) * N + (size_t)bx * 128;
#pragma unroll
    for (int i = 0; i < 8; i++) {
        int row = (i < 4) ? (ty * 4 + i) : (64 + ty * 4 + (i - 4));
#pragma unroll
        for (int jj = 0; jj < 2; jj++) {
            int col = (jj == 0) ? (tx * 4) : (64 + tx * 4);
            const float* bp = bias + (size_t)bx * 128 + col;
            float4 v;
            v.x = acc[i][jj * 4 + 0] + bp[0];
            v.y = acc[i][jj * 4 + 1] + bp[1];
            v.z = acc[i][jj * 4 + 2] + bp[2];
            v.w = acc[i][jj * 4 + 3] + bp[3];
            *(float4*)(Cb + (size_t)row * N + col) = v;
        }
    }
}

// ---------------------------------------------------------------------------
// Build present[2,B,H,NS,D] = concat(layer_past, new k/v from qkv) (float4)
// ---------------------------------------------------------------------------
__global__ __launch_bounds__(256) void build_present(
    const float* __restrict__ past, const float* __restrict__ qkv,
    float* __restrict__ present)
{
    size_t i4 = (size_t)blockIdx.x * 256 + threadIdx.x;   // 4,194,304 float4s
    size_t f = i4 * 4;
    int d = (int)(f & 63);
    size_t r = f >> 6;              // row over [2,B,H,NS]
    int t = (int)(r % NSz); r /= NSz;
    int h = (int)(r % Hz);  r /= Hz;
    int b = (int)(r % Bz);
    int c = (int)(r / Bz);          // 0 = k, 1 = v
    float4 v;
    if (t < Pz) {
        v = *(const float4*)(past +
              ((((size_t)c * Bz + b) * Hz + h) * Pz + t) * Dz + d);
    } else {
        int s = t - Pz;
        v = *(const float4*)(qkv +
              ((size_t)b * Ssz + s) * E3 + (size_t)(c + 1) * Ez + h * Dz + d);
    }
    *(float4*)(present + f) = v;
}

// ---------------------------------------------------------------------------
// Flash-style causal attention. One query row per thread (q, o in regs).
// Block = 128 queries of one (b,h). K/V tiles of 64 in smem, broadcast reads.
// ---------------------------------------------------------------------------
__global__ __launch_bounds__(128) void attn_kernel(
    const float* __restrict__ qkv, const float* __restrict__ present,
    float* __restrict__ attn_out)
{
    const int qt = blockIdx.x;      // 0..7  (q tile of 128)
    const int h  = blockIdx.y;      // 0..15
    const int b  = blockIdx.z;      // 0..3
    const int tid = threadIdx.x;
    const int qi = qt * 128 + tid;  // query index in S

    __shared__ __align__(16) float ks[64][64];
    __shared__ __align__(16) float vs[64][64];

    float q[64], o[64];
    const float* qrow = qkv + ((size_t)(b * Ssz + qi)) * E3 + h * Dz;
#pragma unroll
    for (int d4 = 0; d4 < 16; d4++) {
        float4 t4 = ((const float4*)qrow)[d4];
        q[4 * d4 + 0] = t4.x * 0.125f;   // pre-scale by 1/sqrt(D)
        q[4 * d4 + 1] = t4.y * 0.125f;
        q[4 * d4 + 2] = t4.z * 0.125f;
        q[4 * d4 + 3] = t4.w * 0.125f;
    }
#pragma unroll
    for (int d = 0; d < 64; d++) o[d] = 0.f;
    float m = -1e30f, l = 0.f;

    const float* kbase = present + (((size_t)0 * Bz + b) * Hz + h) * (size_t)NSz * Dz;
    const float* vbase = present + (((size_t)1 * Bz + b) * Hz + h) * (size_t)NSz * Dz;

    const int q_last = Pz + qi;                       // last allowed key (incl.)
    const int t_end = Pz + qt * 128 + 128;            // tile loop bound (<= NS)

    for (int kt = 0; kt < t_end; kt += 64) {
        // cooperative tile load: 2*64*64 floats by 128 threads (float4)
        for (int i = tid; i < 64 * 16; i += 128) {
            int r = i >> 4, c4 = i & 15;
            ((float4*)ks[r])[c4] = ((const float4*)(kbase + (size_t)(kt + r) * 64))[c4];
            ((float4*)vs[r])[c4] = ((const float4*)(vbase + (size_t)(kt + r) * 64))[c4];
        }
        __syncthreads();

#pragma unroll
        for (int c = 0; c < 4; c++) {
            float sreg[16];
            const int jbase = kt + c * 16;
#pragma unroll
            for (int j = 0; j < 16; j++) {
                const float4* krow = (const float4*)ks[c * 16 + j];
                float s = 0.f;
#pragma unroll
                for (int d4 = 0; d4 < 16; d4++) {
                    float4 kv = krow[d4];
                    s += q[4 * d4 + 0] * kv.x + q[4 * d4 + 1] * kv.y
                       + q[4 * d4 + 2] * kv.z + q[4 * d4 + 3] * kv.w;
                }
                sreg[j] = (jbase + j <= q_last) ? s : -1e30f;
            }
            float cmax = sreg[0];
#pragma unroll
            for (int j = 1; j < 16; j++) cmax = fmaxf(cmax, sreg[j]);
            float mnew = fmaxf(m, cmax);
            float alpha = __expf(m - mnew);
            l *= alpha;
#pragma unroll
            for (int d = 0; d < 64; d++) o[d] *= alpha;
#pragma unroll
            for (int j = 0; j < 16; j++) {
                float p = __expf(sreg[j] - mnew);
                l += p;
                const float4* vrow = (const float4*)vs[c * 16 + j];
#pragma unroll
                for (int d4 = 0; d4 < 16; d4++) {
                    float4 vv = vrow[d4];
                    o[4 * d4 + 0] += p * vv.x;
                    o[4 * d4 + 1] += p * vv.y;
                    o[4 * d4 + 2] += p * vv.z;
                    o[4 * d4 + 3] += p * vv.w;
                }
            }
            m = mnew;
        }
        __syncthreads();
    }

    const float inv = 1.f / l;
    float* orow = attn_out + ((size_t)(b * Ssz + qi)) * Ez + h * Dz;
#pragma unroll
    for (int d4 = 0; d4 < 16; d4++) {
        float4 v;
        v.x = o[4 * d4 + 0] * inv;
        v.y = o[4 * d4 + 1] * inv;
        v.z = o[4 * d4 + 2] * inv;
        v.w = o[4 * d4 + 3] * inv;
        ((float4*)orow)[d4] = v;
    }
}

// ---------------------------------------------------------------------------
extern "C" void kernel_launch(void* const* d_in, const int* in_sizes, int n_in,
                              void* d_out, int out_size)
{
    const float* x      = (const float*)d_in[0];
    const float* past   = (const float*)d_in[1];
    const float* w_attn = (const float*)d_in[2];
    const float* b_attn = (const float*)d_in[3];
    const float* w_proj = (const float*)d_in[4];
    const float* b_proj = (const float*)d_in[5];
    float* out = (float*)d_out;
    float* present = out + (size_t)Mz * Ez;   // out (4.19M) then present (16.78M)

    float *qkv, *attn;
    cudaGetSymbolAddress((void**)&qkv,  g_qkv);
    cudaGetSymbolAddress((void**)&attn, g_attn);

    // 1) qkv = x @ w_attn + b_attn          [4096,3072]
    sgemm_bias<<<dim3(E3 / 128, Mz / 128), 256>>>(x, w_attn, b_attn, qkv,
                                                  Mz, E3, Ez);
    // 2) present = concat(past, new k/v)
    build_present<<<16384, 256>>>(past, qkv, present);
    // 3) attention -> merged heads          [4096,1024]
    attn_kernel<<<dim3(Ssz / 128, Hz, Bz), 128>>>(qkv, present, attn);
    // 4) out = attn @ w_proj + b_proj       [4096,1024]
    sgemm_bias<<<dim3(Ez / 128, Mz / 128), 256>>>(attn, w_proj, b_proj, out,
                                                  Mz, Ez, Ez);
}

// round 6
// speedup vs baseline: 1.1702x; 1.1702x over previous
#include <cuda_runtime.h>
#include <cuda_bf16.h>
#include <cstdint>
#include <cstddef>

#define Bz   4
#define Ssz  1024
#define Pz   1024
#define Ez   1024
#define Hz   16
#define Dz   64
#define NSz  2048
#define Mz   4096
#define E3   3072

// ---------------- scratch (__device__ globals; no cudaMalloc) ---------------
__device__ __align__(16) float g_qkv[(size_t)Mz * E3];
__device__ __align__(16) float g_attn[(size_t)Mz * Ez];
__device__ __align__(16) __nv_bfloat16 g_ah[(size_t)Mz * Ez];
__device__ __align__(16) __nv_bfloat16 g_al[(size_t)Mz * Ez];
__device__ __align__(16) __nv_bfloat16 g_wah[(size_t)E3 * Ez];
__device__ __align__(16) __nv_bfloat16 g_wal[(size_t)E3 * Ez];
__device__ __align__(16) __nv_bfloat16 g_wph[(size_t)Ez * Ez];
__device__ __align__(16) __nv_bfloat16 g_wpl[(size_t)Ez * Ez];

// ---------------- PTX helpers (sm_80-class only: HMMA/ldmatrix/cp.async) ----
__device__ __forceinline__ uint32_t smem_u32(const void* p) {
    uint32_t a;
    asm("{ .reg .u64 t; cvta.to.shared.u64 t, %1; cvt.u32.u64 %0, t; }"
        : "=r"(a) : "l"(p));
    return a;
}
#define CP_ASYNC16(dst, src) \
    asm volatile("cp.async.cg.shared.global [%0], [%1], 16;" \
                 :: "r"(dst), "l"(src) : "memory")
#define CP_COMMIT() asm volatile("cp.async.commit_group;" ::: "memory")
#define CP_WAIT1()  asm volatile("cp.async.wait_group 1;" ::: "memory")

#define LDSM4(r, a) \
    asm volatile("ldmatrix.sync.aligned.m8n8.x4.shared.b16 {%0,%1,%2,%3}, [%4];" \
                 : "=r"((r)[0]), "=r"((r)[1]), "=r"((r)[2]), "=r"((r)[3]) : "r"(a))

#define MMA16816(c, a, b0, b1) \
    asm volatile("mma.sync.aligned.m16n8k16.row.col.f32.bf16.bf16.f32 " \
                 "{%0,%1,%2,%3},{%4,%5,%6,%7},{%8,%9},{%0,%1,%2,%3};" \
                 : "+f"((c)[0]), "+f"((c)[1]), "+f"((c)[2]), "+f"((c)[3]) \
                 : "r"((a)[0]), "r"((a)[1]), "r"((a)[2]), "r"((a)[3]), \
                   "r"(b0), "r"(b1))

#define SW128(o) ((o) ^ (((o) >> 3) & 0x70))

// ---------------------------------------------------------------------------
// Split fp32 -> bf16 hi + bf16 lo
// ---------------------------------------------------------------------------
__global__ __launch_bounds__(256) void split_hl(
    const float* __restrict__ src, __nv_bfloat16* __restrict__ hi,
    __nv_bfloat16* __restrict__ lo)
{
    size_t i = (size_t)blockIdx.x * 256 + threadIdx.x;
    float4 v = ((const float4*)src)[i];
    __nv_bfloat16 h0 = __float2bfloat16(v.x), h1 = __float2bfloat16(v.y);
    __nv_bfloat16 h2 = __float2bfloat16(v.z), h3 = __float2bfloat16(v.w);
    __nv_bfloat16 l0 = __float2bfloat16(v.x - __bfloat162float(h0));
    __nv_bfloat16 l1 = __float2bfloat16(v.y - __bfloat162float(h1));
    __nv_bfloat16 l2 = __float2bfloat16(v.z - __bfloat162float(h2));
    __nv_bfloat16 l3 = __float2bfloat16(v.w - __bfloat162float(h3));
    ((__nv_bfloat162*)hi)[2 * i]     = __nv_bfloat162(h0, h1);
    ((__nv_bfloat162*)hi)[2 * i + 1] = __nv_bfloat162(h2, h3);
    ((__nv_bfloat162*)lo)[2 * i]     = __nv_bfloat162(l0, l1);
    ((__nv_bfloat162*)lo)[2 * i + 1] = __nv_bfloat162(l2, l3);
}

// ---------------------------------------------------------------------------
// Transpose + split: src [K,N] f32 -> hi/lo [N,K] bf16
// ---------------------------------------------------------------------------
__global__ __launch_bounds__(256) void splitT(
    const float* __restrict__ src, __nv_bfloat16* __restrict__ hi,
    __nv_bfloat16* __restrict__ lo, int K, int N)
{
    __shared__ float t[32][33];
    int n0 = blockIdx.x * 32, k0 = blockIdx.y * 32;
    int tx = threadIdx.x, ty = threadIdx.y;
#pragma unroll
    for (int i = 0; i < 32; i += 8)
        t[ty + i][tx] = src[(size_t)(k0 + ty + i) * N + (n0 + tx)];
    __syncthreads();
#pragma unroll
    for (int i = 0; i < 32; i += 8) {
        int n = n0 + ty + i, k = k0 + tx;
        float v = t[tx][ty + i];
        __nv_bfloat16 h = __float2bfloat16(v);
        hi[(size_t)n * K + k] = h;
        lo[(size_t)n * K + k] = __float2bfloat16(v - __bfloat162float(h));
    }
}

// ---------------------------------------------------------------------------
// HMMA bf16-split GEMM: C[M,N] = A[M,K]@B[K,N] + bias
// Ah/Al [M,K] bf16, Bh/Bl [N,K] bf16 (pre-transposed).
// CTA tile 128x128, BK=64, SW128 atoms, cp.async double buffer.
// 8 warps: wm = wid&3 (4 x 32 rows), wn = wid>>2 (2 x 64 cols).
// ---------------------------------------------------------------------------
__global__ __launch_bounds__(256) void gemm_mma(
    const __nv_bfloat16* __restrict__ Ah, const __nv_bfloat16* __restrict__ Al,
    const __nv_bfloat16* __restrict__ Bh, const __nv_bfloat16* __restrict__ Bl,
    const float* __restrict__ bias, float* __restrict__ C, int N, int K)
{
    extern __shared__ __align__(1024) char smem[];   // 2 stages x 4 tiles x 16KB
    const uint32_t sb = smem_u32(smem);
    const int tid = threadIdx.x;
    const int wid = tid >> 5, lane = tid & 31;
    const int wm = wid & 3, wn = wid >> 2;
    const int bn = blockIdx.x, bm = blockIdx.y;

    const char* gA[2] = { (const char*)(Ah + (size_t)(bm * 128) * K),
                          (const char*)(Al + (size_t)(bm * 128) * K) };
    const char* gB[2] = { (const char*)(Bh + (size_t)(bn * 128) * K),
                          (const char*)(Bl + (size_t)(bn * 128) * K) };
    const int Kb = K * 2;               // row bytes in gmem
    const int r = tid >> 3;             // 0..31 used as row/8 pattern below
    const int nck = K >> 6;

    // per-thread copy pattern: 16 x 16B per tile-quad stage
    // tile copy: each thread does 4 x cp.async of 16B: rows tid>>3 + 32*j? No:
    // i = tid + 256*j, row = i>>3 (0..127), colbyte = (i&7)*16 (0..112)
    auto copy_stage = [&](int buf, int ck) {
        const int koff = ck * 128;      // 64 elements * 2B
#pragma unroll
        for (int t = 0; t < 4; t++) {
            const char* g = (t < 2 ? gA[t] : gB[t - 2]) + koff;
            uint32_t s = sb + ((buf << 2) + t) * 16384;
#pragma unroll
            for (int j = 0; j < 4; j++) {
                int i = tid + 256 * j;
                int rr = i >> 3, cc = (i & 7) << 4;
                CP_ASYNC16(s + SW128(rr * 128 + cc), g + (size_t)rr * Kb + cc);
            }
        }
    };
    (void)r;

    copy_stage(0, 0); CP_COMMIT();
    if (nck > 1) copy_stage(1, 1);
    CP_COMMIT();

    float c[2][8][4];
#pragma unroll
    for (int mf = 0; mf < 2; mf++)
#pragma unroll
        for (int nf = 0; nf < 8; nf++)
#pragma unroll
            for (int k = 0; k < 4; k++) c[mf][nf][k] = 0.f;

    const int lrow = lane & 15, lhalf = lane >> 4;   // ldmatrix addressing

    for (int ck = 0; ck < nck; ck++) {
        CP_WAIT1();
        __syncthreads();
        const int buf = ck & 1;
        const uint32_t tAh = sb + ((buf << 2) + 0) * 16384;
        const uint32_t tAl = sb + ((buf << 2) + 1) * 16384;
        const uint32_t tBh = sb + ((buf << 2) + 2) * 16384;
        const uint32_t tBl = sb + ((buf << 2) + 3) * 16384;

#pragma unroll
        for (int k16 = 0; k16 < 4; k16++) {
            const int kb = k16 * 32 + lhalf * 16;    // byte col of 8-elem group
            uint32_t ah[2][4], al[2][4], bh[4][4], bl[4][4];
#pragma unroll
            for (int mf = 0; mf < 2; mf++) {
                int row = wm * 32 + mf * 16 + lrow;
                LDSM4(ah[mf], tAh + SW128(row * 128 + kb));
                LDSM4(al[mf], tAl + SW128(row * 128 + kb));
            }
#pragma unroll
            for (int bp = 0; bp < 4; bp++) {
                int row = wn * 64 + bp * 16 + lrow;
                LDSM4(bh[bp], tBh + SW128(row * 128 + kb));
                LDSM4(bl[bp], tBl + SW128(row * 128 + kb));
            }
#pragma unroll
            for (int mf = 0; mf < 2; mf++)
#pragma unroll
                for (int nf = 0; nf < 8; nf++) {
                    const int bp = nf >> 1, od = nf & 1;
                    MMA16816(c[mf][nf], ah[mf], bh[bp][od], bh[bp][od + 2]);
                    MMA16816(c[mf][nf], al[mf], bh[bp][od], bh[bp][od + 2]);
                    MMA16816(c[mf][nf], ah[mf], bl[bp][od], bl[bp][od + 2]);
                }
        }
        __syncthreads();
        if (ck + 2 < nck) copy_stage(buf, ck + 2);
        CP_COMMIT();                                  // empty group OK
    }

    // epilogue: c-frag thread l: rows l>>2 (+0/+8), cols 2*(l&3) (+0/+1)
    const int crow = bm * 128 + wm * 32 + (lane >> 2);
    const int ccol = bn * 128 + wn * 64 + (lane & 3) * 2;
    const float* bp = bias + ccol;
#pragma unroll
    for (int mf = 0; mf < 2; mf++) {
#pragma unroll
        for (int nf = 0; nf < 8; nf++) {
            float2 bv = *(const float2*)(bp + nf * 8);
            float2 v0 = { c[mf][nf][0] + bv.x, c[mf][nf][1] + bv.y };
            float2 v1 = { c[mf][nf][2] + bv.x, c[mf][nf][3] + bv.y };
            size_t r0 = (size_t)(crow + mf * 16) * N + ccol + nf * 8;
            *(float2*)(C + r0) = v0;
            *(float2*)(C + r0 + 8 * (size_t)N) = v1;
        }
    }
}

// ---------------------------------------------------------------------------
// present[2,B,H,NS,D] = concat(layer_past, new k/v)
// ---------------------------------------------------------------------------
__global__ __launch_bounds__(256) void build_present(
    const float* __restrict__ past, const float* __restrict__ qkv,
    float* __restrict__ present)
{
    size_t i4 = (size_t)blockIdx.x * 256 + threadIdx.x;
    size_t f = i4 * 4;
    int d = (int)(f & 63);
    size_t r = f >> 6;
    int t = (int)(r % NSz); r /= NSz;
    int h = (int)(r % Hz);  r /= Hz;
    int b = (int)(r % Bz);
    int c = (int)(r / Bz);
    float4 v;
    if (t < Pz) {
        v = *(const float4*)(past + ((((size_t)c * Bz + b) * Hz + h) * Pz + t) * Dz + d);
    } else {
        int s = t - Pz;
        v = *(const float4*)(qkv + ((size_t)b * Ssz + s) * E3 + (size_t)(c + 1) * Ez + h * Dz + d);
    }
    *(float4*)(present + f) = v;
}

// ---------------------------------------------------------------------------
// Flash-style causal attention (unchanged this round)
// ---------------------------------------------------------------------------
__global__ __launch_bounds__(128) void attn_kernel(
    const float* __restrict__ qkv, const float* __restrict__ present,
    float* __restrict__ attn_out)
{
    const int qt = blockIdx.x, h = blockIdx.y, b = blockIdx.z;
    const int tid = threadIdx.x;
    const int qi = qt * 128 + tid;

    __shared__ __align__(16) float ks[64][64];
    __shared__ __align__(16) float vs[64][64];

    float q[64], o[64];
    const float* qrow = qkv + ((size_t)(b * Ssz + qi)) * E3 + h * Dz;
#pragma unroll
    for (int d4 = 0; d4 < 16; d4++) {
        float4 t4 = ((const float4*)qrow)[d4];
        q[4 * d4 + 0] = t4.x * 0.125f;
        q[4 * d4 + 1] = t4.y * 0.125f;
        q[4 * d4 + 2] = t4.z * 0.125f;
        q[4 * d4 + 3] = t4.w * 0.125f;
    }
#pragma unroll
    for (int d = 0; d < 64; d++) o[d] = 0.f;
    float m = -1e30f, l = 0.f;

    const float* kbase = present + (((size_t)0 * Bz + b) * Hz + h) * (size_t)NSz * Dz;
    const float* vbase = present + (((size_t)1 * Bz + b) * Hz + h) * (size_t)NSz * Dz;
    const int q_last = Pz + qi;
    const int t_end = Pz + qt * 128 + 128;

    for (int kt = 0; kt < t_end; kt += 64) {
        for (int i = tid; i < 64 * 16; i += 128) {
            int r = i >> 4, c4 = i & 15;
            ((float4*)ks[r])[c4] = ((const float4*)(kbase + (size_t)(kt + r) * 64))[c4];
            ((float4*)vs[r])[c4] = ((const float4*)(vbase + (size_t)(kt + r) * 64))[c4];
        }
        __syncthreads();
#pragma unroll
        for (int c = 0; c < 4; c++) {
            float sreg[16];
            const int jbase = kt + c * 16;
#pragma unroll
            for (int j = 0; j < 16; j++) {
                const float4* krow = (const float4*)ks[c * 16 + j];
                float s = 0.f;
#pragma unroll
                for (int d4 = 0; d4 < 16; d4++) {
                    float4 kv = krow[d4];
                    s += q[4 * d4 + 0] * kv.x + q[4 * d4 + 1] * kv.y
                       + q[4 * d4 + 2] * kv.z + q[4 * d4 + 3] * kv.w;
                }
                sreg[j] = (jbase + j <= q_last) ? s : -1e30f;
            }
            float cmax = sreg[0];
#pragma unroll
            for (int j = 1; j < 16; j++) cmax = fmaxf(cmax, sreg[j]);
            float mnew = fmaxf(m, cmax);
            float alpha = __expf(m - mnew);
            l *= alpha;
#pragma unroll
            for (int d = 0; d < 64; d++) o[d] *= alpha;
#pragma unroll
            for (int j = 0; j < 16; j++) {
                float p = __expf(sreg[j] - mnew);
                l += p;
                const float4* vrow = (const float4*)vs[c * 16 + j];
#pragma unroll
                for (int d4 = 0; d4 < 16; d4++) {
                    float4 vv = vrow[d4];
                    o[4 * d4 + 0] += p * vv.x;
                    o[4 * d4 + 1] += p * vv.y;
                    o[4 * d4 + 2] += p * vv.z;
                    o[4 * d4 + 3] += p * vv.w;
                }
            }
            m = mnew;
        }
        __syncthreads();
    }

    const float inv = 1.f / l;
    float* orow = attn_out + ((size_t)(b * Ssz + qi)) * Ez + h * Dz;
#pragma unroll
    for (int d4 = 0; d4 < 16; d4++) {
        float4 v;
        v.x = o[4 * d4 + 0] * inv;
        v.y = o[4 * d4 + 1] * inv;
        v.z = o[4 * d4 + 2] * inv;
        v.w = o[4 * d4 + 3] * inv;
        ((float4*)orow)[d4] = v;
    }
}

// ---------------------------------------------------------------------------
extern "C" void kernel_launch(void* const* d_in, const int* in_sizes, int n_in,
                              void* d_out, int out_size)
{
    const float* x      = (const float*)d_in[0];
    const float* past   = (const float*)d_in[1];
    const float* w_attn = (const float*)d_in[2];
    const float* b_attn = (const float*)d_in[3];
    const float* w_proj = (const float*)d_in[4];
    const float* b_proj = (const float*)d_in[5];
    float* out = (float*)d_out;
    float* present = out + (size_t)Mz * Ez;

    float *qkv, *attn;
    __nv_bfloat16 *ah, *al, *wah, *wal, *wph, *wpl;
    cudaGetSymbolAddress((void**)&qkv,  g_qkv);
    cudaGetSymbolAddress((void**)&attn, g_attn);
    cudaGetSymbolAddress((void**)&ah,  g_ah);
    cudaGetSymbolAddress((void**)&al,  g_al);
    cudaGetSymbolAddress((void**)&wah, g_wah);
    cudaGetSymbolAddress((void**)&wal, g_wal);
    cudaGetSymbolAddress((void**)&wph, g_wph);
    cudaGetSymbolAddress((void**)&wpl, g_wpl);

    static const int SMEM_GEMM = 2 * 4 * 16384;   // 131072
    cudaFuncSetAttribute(gemm_mma, cudaFuncAttributeMaxDynamicSharedMemorySize, SMEM_GEMM);

    // 0) weight transpose+split
    splitT<<<dim3(E3 / 32, Ez / 32), dim3(32, 8)>>>(w_attn, wah, wal, Ez, E3);
    splitT<<<dim3(Ez / 32, Ez / 32), dim3(32, 8)>>>(w_proj, wph, wpl, Ez, Ez);
    // 1) split x
    split_hl<<<(Mz * Ez) / 1024, 256>>>(x, ah, al);
    // 2) qkv = x @ w_attn + b_attn  (HMMA)
    gemm_mma<<<dim3(E3 / 128, Mz / 128), 256, SMEM_GEMM>>>(ah, al, wah, wal,
                                                           b_attn, qkv, E3, Ez);
    // 3) present
    build_present<<<16384, 256>>>(past, qkv, present);
    // 4) attention
    attn_kernel<<<dim3(Ssz / 128, Hz, Bz), 128>>>(qkv, present, attn);
    // 5) split attn
    split_hl<<<(Mz * Ez) / 1024, 256>>>(attn, ah, al);
    // 6) out = attn @ w_proj + b_proj  (HMMA)
    gemm_mma<<<dim3(Ez / 128, Mz / 128), 256, SMEM_GEMM>>>(ah, al, wph, wpl,
                                                           b_proj, out, Ez, Ez);
}

// round 7
// speedup vs baseline: 4.5436x; 3.8829x over previous
#include <cuda_runtime.h>
#include <cuda_bf16.h>
#include <cstdint>
#include <cstddef>

#define Bz   4
#define Ssz  1024
#define Pz   1024
#define Ez   1024
#define Hz   16
#define Dz   64
#define NSz  2048
#define Mz   4096
#define E3   3072

// ---------------- scratch ---------------------------------------------------
__device__ __align__(16) float g_qkv[(size_t)Mz * E3];
__device__ __align__(16) float g_attn[(size_t)Mz * Ez];
__device__ __align__(16) __nv_bfloat16 g_ah[(size_t)Mz * Ez];
__device__ __align__(16) __nv_bfloat16 g_al[(size_t)Mz * Ez];
__device__ __align__(16) __nv_bfloat16 g_wah[(size_t)E3 * Ez];
__device__ __align__(16) __nv_bfloat16 g_wal[(size_t)E3 * Ez];
__device__ __align__(16) __nv_bfloat16 g_wph[(size_t)Ez * Ez];
__device__ __align__(16) __nv_bfloat16 g_wpl[(size_t)Ez * Ez];
__device__ __align__(16) __nv_bfloat16 g_qh[(size_t)Bz * Hz * Ssz * Dz];
__device__ __align__(16) __nv_bfloat16 g_ql[(size_t)Bz * Hz * Ssz * Dz];
__device__ __align__(16) __nv_bfloat16 g_kh[(size_t)Bz * Hz * NSz * Dz];
__device__ __align__(16) __nv_bfloat16 g_kl[(size_t)Bz * Hz * NSz * Dz];
__device__ __align__(16) __nv_bfloat16 g_vh[(size_t)Bz * Hz * NSz * Dz];
__device__ __align__(16) __nv_bfloat16 g_vl[(size_t)Bz * Hz * NSz * Dz];

// ---------------- PTX helpers ----------------------------------------------
__device__ __forceinline__ uint32_t smem_u32(const void* p) {
    uint32_t a;
    asm("{ .reg .u64 t; cvta.to.shared.u64 t, %1; cvt.u32.u64 %0, t; }"
        : "=r"(a) : "l"(p));
    return a;
}
#define CP_ASYNC16(dst, src) \
    asm volatile("cp.async.cg.shared.global [%0], [%1], 16;" \
                 :: "r"(dst), "l"(src) : "memory")
#define CP_COMMIT() asm volatile("cp.async.commit_group;" ::: "memory")
#define CP_WAIT1()  asm volatile("cp.async.wait_group 1;" ::: "memory")

#define LDSM4(r, a) \
    asm volatile("ldmatrix.sync.aligned.m8n8.x4.shared.b16 {%0,%1,%2,%3}, [%4];" \
                 : "=r"((r)[0]), "=r"((r)[1]), "=r"((r)[2]), "=r"((r)[3]) : "r"(a))
#define LDSM4T(r, a) \
    asm volatile("ldmatrix.sync.aligned.m8n8.x4.trans.shared.b16 {%0,%1,%2,%3}, [%4];" \
                 : "=r"((r)[0]), "=r"((r)[1]), "=r"((r)[2]), "=r"((r)[3]) : "r"(a))

#define MMA16816(c, a, b0, b1) \
    asm volatile("mma.sync.aligned.m16n8k16.row.col.f32.bf16.bf16.f32 " \
                 "{%0,%1,%2,%3},{%4,%5,%6,%7},{%8,%9},{%0,%1,%2,%3};" \
                 : "+f"((c)[0]), "+f"((c)[1]), "+f"((c)[2]), "+f"((c)[3]) \
                 : "r"((a)[0]), "r"((a)[1]), "r"((a)[2]), "r"((a)[3]), \
                   "r"(b0), "r"(b1))

#define SW128(o) ((o) ^ (((o) >> 3) & 0x70))

__device__ __forceinline__ void packhl(float f0, float f1, uint32_t& h, uint32_t& l) {
    __nv_bfloat16 h0 = __float2bfloat16(f0), h1 = __float2bfloat16(f1);
    __nv_bfloat16 l0 = __float2bfloat16(f0 - __bfloat162float(h0));
    __nv_bfloat16 l1 = __float2bfloat16(f1 - __bfloat162float(h1));
    __nv_bfloat162 hv(h0, h1), lv(l0, l1);
    h = *(uint32_t*)&hv;
    l = *(uint32_t*)&lv;
}

// ---------------------------------------------------------------------------
// Split fp32 -> bf16 hi + bf16 lo (elementwise float4)
// ---------------------------------------------------------------------------
__global__ __launch_bounds__(256) void split_hl(
    const float* __restrict__ src, __nv_bfloat16* __restrict__ hi,
    __nv_bfloat16* __restrict__ lo)
{
    size_t i = (size_t)blockIdx.x * 256 + threadIdx.x;
    float4 v = ((const float4*)src)[i];
    __nv_bfloat16 h0 = __float2bfloat16(v.x), h1 = __float2bfloat16(v.y);
    __nv_bfloat16 h2 = __float2bfloat16(v.z), h3 = __float2bfloat16(v.w);
    __nv_bfloat16 l0 = __float2bfloat16(v.x - __bfloat162float(h0));
    __nv_bfloat16 l1 = __float2bfloat16(v.y - __bfloat162float(h1));
    __nv_bfloat16 l2 = __float2bfloat16(v.z - __bfloat162float(h2));
    __nv_bfloat16 l3 = __float2bfloat16(v.w - __bfloat162float(h3));
    ((__nv_bfloat162*)hi)[2 * i]     = __nv_bfloat162(h0, h1);
    ((__nv_bfloat162*)hi)[2 * i + 1] = __nv_bfloat162(h2, h3);
    ((__nv_bfloat162*)lo)[2 * i]     = __nv_bfloat162(l0, l1);
    ((__nv_bfloat162*)lo)[2 * i + 1] = __nv_bfloat162(l2, l3);
}

// ---------------------------------------------------------------------------
// Gather+split Q: qkv[b*S+s][h*64+d] * 0.125 -> qh/ql[((b*H+h)*S+s)*64+d]
// ---------------------------------------------------------------------------
__global__ __launch_bounds__(256) void split_q(
    const float* __restrict__ qkv, __nv_bfloat16* __restrict__ qh,
    __nv_bfloat16* __restrict__ ql)
{
    size_t i = (size_t)blockIdx.x * 256 + threadIdx.x;   // over elems/4
    size_t e = i * 4;
    int d = (int)(e & 63);
    size_t r = e >> 6;
    int s = (int)(r % Ssz); r /= Ssz;
    int h = (int)(r % Hz);
    int b = (int)(r / Hz);
    float4 v = *(const float4*)(qkv + ((size_t)(b * Ssz + s)) * E3 + h * 64 + d);
    v.x *= 0.125f; v.y *= 0.125f; v.z *= 0.125f; v.w *= 0.125f;
    __nv_bfloat16 h0 = __float2bfloat16(v.x), h1 = __float2bfloat16(v.y);
    __nv_bfloat16 h2 = __float2bfloat16(v.z), h3 = __float2bfloat16(v.w);
    __nv_bfloat16 l0 = __float2bfloat16(v.x - __bfloat162float(h0));
    __nv_bfloat16 l1 = __float2bfloat16(v.y - __bfloat162float(h1));
    __nv_bfloat16 l2 = __float2bfloat16(v.z - __bfloat162float(h2));
    __nv_bfloat16 l3 = __float2bfloat16(v.w - __bfloat162float(h3));
    ((__nv_bfloat162*)qh)[2 * i]     = __nv_bfloat162(h0, h1);
    ((__nv_bfloat162*)qh)[2 * i + 1] = __nv_bfloat162(h2, h3);
    ((__nv_bfloat162*)ql)[2 * i]     = __nv_bfloat162(l0, l1);
    ((__nv_bfloat162*)ql)[2 * i + 1] = __nv_bfloat162(l2, l3);
}

// ---------------------------------------------------------------------------
// Transpose + split weights: src [K,N] f32 -> hi/lo [N,K] bf16
// ---------------------------------------------------------------------------
__global__ __launch_bounds__(256) void splitT(
    const float* __restrict__ src, __nv_bfloat16* __restrict__ hi,
    __nv_bfloat16* __restrict__ lo, int K, int N)
{
    __shared__ float t[32][33];
    int n0 = blockIdx.x * 32, k0 = blockIdx.y * 32;
    int tx = threadIdx.x, ty = threadIdx.y;
#pragma unroll
    for (int i = 0; i < 32; i += 8)
        t[ty + i][tx] = src[(size_t)(k0 + ty + i) * N + (n0 + tx)];
    __syncthreads();
#pragma unroll
    for (int i = 0; i < 32; i += 8) {
        int n = n0 + ty + i, k = k0 + tx;
        float v = t[tx][ty + i];
        __nv_bfloat16 h = __float2bfloat16(v);
        hi[(size_t)n * K + k] = h;
        lo[(size_t)n * K + k] = __float2bfloat16(v - __bfloat162float(h));
    }
}

// ---------------------------------------------------------------------------
// HMMA bf16-split GEMM (validated R6)
// ---------------------------------------------------------------------------
__global__ __launch_bounds__(256) void gemm_mma(
    const __nv_bfloat16* __restrict__ Ah, const __nv_bfloat16* __restrict__ Al,
    const __nv_bfloat16* __restrict__ Bh, const __nv_bfloat16* __restrict__ Bl,
    const float* __restrict__ bias, float* __restrict__ C, int N, int K)
{
    extern __shared__ __align__(1024) char smem[];
    const uint32_t sb = smem_u32(smem);
    const int tid = threadIdx.x;
    const int wid = tid >> 5, lane = tid & 31;
    const int wm = wid & 3, wn = wid >> 2;
    const int bn = blockIdx.x, bm = blockIdx.y;

    const char* gA[2] = { (const char*)(Ah + (size_t)(bm * 128) * K),
                          (const char*)(Al + (size_t)(bm * 128) * K) };
    const char* gB[2] = { (const char*)(Bh + (size_t)(bn * 128) * K),
                          (const char*)(Bl + (size_t)(bn * 128) * K) };
    const int Kb = K * 2;
    const int nck = K >> 6;

    auto copy_stage = [&](int buf, int ck) {
        const int koff = ck * 128;
#pragma unroll
        for (int t = 0; t < 4; t++) {
            const char* g = (t < 2 ? gA[t] : gB[t - 2]) + koff;
            uint32_t s = sb + ((buf << 2) + t) * 16384;
#pragma unroll
            for (int j = 0; j < 4; j++) {
                int i = tid + 256 * j;
                int rr = i >> 3, cc = (i & 7) << 4;
                CP_ASYNC16(s + SW128(rr * 128 + cc), g + (size_t)rr * Kb + cc);
            }
        }
    };

    copy_stage(0, 0); CP_COMMIT();
    if (nck > 1) copy_stage(1, 1);
    CP_COMMIT();

    float c[2][8][4];
#pragma unroll
    for (int mf = 0; mf < 2; mf++)
#pragma unroll
        for (int nf = 0; nf < 8; nf++)
#pragma unroll
            for (int k = 0; k < 4; k++) c[mf][nf][k] = 0.f;

    const int lrow = lane & 15, lhalf = lane >> 4;

    for (int ck = 0; ck < nck; ck++) {
        CP_WAIT1();
        __syncthreads();
        const int buf = ck & 1;
        const uint32_t tAh = sb + ((buf << 2) + 0) * 16384;
        const uint32_t tAl = sb + ((buf << 2) + 1) * 16384;
        const uint32_t tBh = sb + ((buf << 2) + 2) * 16384;
        const uint32_t tBl = sb + ((buf << 2) + 3) * 16384;

#pragma unroll
        for (int k16 = 0; k16 < 4; k16++) {
            const int kb = k16 * 32 + lhalf * 16;
            uint32_t ah[2][4], al[2][4], bh[4][4], bl[4][4];
#pragma unroll
            for (int mf = 0; mf < 2; mf++) {
                int row = wm * 32 + mf * 16 + lrow;
                LDSM4(ah[mf], tAh + SW128(row * 128 + kb));
                LDSM4(al[mf], tAl + SW128(row * 128 + kb));
            }
#pragma unroll
            for (int bp = 0; bp < 4; bp++) {
                int row = wn * 64 + bp * 16 + lrow;
                LDSM4(bh[bp], tBh + SW128(row * 128 + kb));
                LDSM4(bl[bp], tBl + SW128(row * 128 + kb));
            }
#pragma unroll
            for (int mf = 0; mf < 2; mf++)
#pragma unroll
                for (int nf = 0; nf < 8; nf++) {
                    const int bp = nf >> 1, od = nf & 1;
                    MMA16816(c[mf][nf], ah[mf], bh[bp][od], bh[bp][od + 2]);
                    MMA16816(c[mf][nf], al[mf], bh[bp][od], bh[bp][od + 2]);
                    MMA16816(c[mf][nf], ah[mf], bl[bp][od], bl[bp][od + 2]);
                }
        }
        __syncthreads();
        if (ck + 2 < nck) copy_stage(buf, ck + 2);
        CP_COMMIT();
    }

    const int crow = bm * 128 + wm * 32 + (lane >> 2);
    const int ccol = bn * 128 + wn * 64 + (lane & 3) * 2;
    const float* bp = bias + ccol;
#pragma unroll
    for (int mf = 0; mf < 2; mf++) {
#pragma unroll
        for (int nf = 0; nf < 8; nf++) {
            float2 bv = *(const float2*)(bp + nf * 8);
            float2 v0 = { c[mf][nf][0] + bv.x, c[mf][nf][1] + bv.y };
            float2 v1 = { c[mf][nf][2] + bv.x, c[mf][nf][3] + bv.y };
            size_t r0 = (size_t)(crow + mf * 16) * N + ccol + nf * 8;
            *(float2*)(C + r0) = v0;
            *(float2*)(C + r0 + 8 * (size_t)N) = v1;
        }
    }
}

// ---------------------------------------------------------------------------
// present[2,B,H,NS,D] = concat(layer_past, new k/v)
// ---------------------------------------------------------------------------
__global__ __launch_bounds__(256) void build_present(
    const float* __restrict__ past, const float* __restrict__ qkv,
    float* __restrict__ present)
{
    size_t i4 = (size_t)blockIdx.x * 256 + threadIdx.x;
    size_t f = i4 * 4;
    int d = (int)(f & 63);
    size_t r = f >> 6;
    int t = (int)(r % NSz); r /= NSz;
    int h = (int)(r % Hz);  r /= Hz;
    int b = (int)(r % Bz);
    int c = (int)(r / Bz);
    float4 v;
    if (t < Pz) {
        v = *(const float4*)(past + ((((size_t)c * Bz + b) * Hz + h) * Pz + t) * Dz + d);
    } else {
        int s = t - Pz;
        v = *(const float4*)(qkv + ((size_t)b * Ssz + s) * E3 + (size_t)(c + 1) * Ez + h * Dz + d);
    }
    *(float4*)(present + f) = v;
}

// ---------------------------------------------------------------------------
// HMMA flash attention. 8 warps x 16 q-rows = 128 q/CTA, K/V tiles of 64.
// S = Qh*Kh + Ql*Kh + Qh*Kl ; P split hi/lo in regs ; PV same 3-pass.
// smem: Qh(16K) Ql(16K) | 2 stages x {Kh,Kl,Vh,Vl} x 8K = 96KB.
// ---------------------------------------------------------------------------
__global__ __launch_bounds__(256) void attn_mma(
    const __nv_bfloat16* __restrict__ qh_g, const __nv_bfloat16* __restrict__ ql_g,
    const __nv_bfloat16* __restrict__ kh_g, const __nv_bfloat16* __restrict__ kl_g,
    const __nv_bfloat16* __restrict__ vh_g, const __nv_bfloat16* __restrict__ vl_g,
    float* __restrict__ attn_out)
{
    extern __shared__ __align__(1024) char smem[];
    const uint32_t sb = smem_u32(smem);
    const int tid = threadIdx.x, wid = tid >> 5, lane = tid & 31;
    const int qt = blockIdx.x, h = blockIdx.y, b = blockIdx.z;
    const int lrow = lane & 15, lhalf = lane >> 4;

    const size_t bh = (size_t)(b * Hz + h);
    const char* qhg = (const char*)(qh_g + (bh * Ssz + (size_t)qt * 128) * Dz);
    const char* qlg = (const char*)(ql_g + (bh * Ssz + (size_t)qt * 128) * Dz);
    const char* kvg[4] = { (const char*)(kh_g + bh * NSz * Dz),
                           (const char*)(kl_g + bh * NSz * Dz),
                           (const char*)(vh_g + bh * NSz * Dz),
                           (const char*)(vl_g + bh * NSz * Dz) };

    const int diag0 = Pz + qt * 128;            // kt at which diagonal enters
    const int ntiles = (diag0 + 128) >> 6;

    auto copy_kv = [&](int buf, int t) {
        const size_t off = (size_t)t * 64 * 128;
#pragma unroll
        for (int p = 0; p < 4; p++) {
            uint32_t s = sb + 32768 + buf * 32768 + p * 8192;
            const char* g = kvg[p] + off;
#pragma unroll
            for (int j = 0; j < 2; j++) {
                int i = tid + 256 * j;
                int r = i >> 3, c = (i & 7) << 4;
                CP_ASYNC16(s + SW128(r * 128 + c), g + r * 128 + c);
            }
        }
    };

    // Q tiles (group 0) + KV stage 0 (group 0), stage 1 (group 1)
#pragma unroll
    for (int j = 0; j < 4; j++) {
        int i = tid + 256 * j;
        int r = i >> 3, c = (i & 7) << 4;
        CP_ASYNC16(sb + SW128(r * 128 + c), qhg + r * 128 + c);
        CP_ASYNC16(sb + 16384 + SW128(r * 128 + c), qlg + r * 128 + c);
    }
    copy_kv(0, 0); CP_COMMIT();
    copy_kv(1, 1); CP_COMMIT();

    CP_WAIT1();
    __syncthreads();

    // cache Q A-frags (rows wid*16 + lrow)
    uint32_t qfh[4][4], qfl[4][4];
#pragma unroll
    for (int kk = 0; kk < 4; kk++) {
        uint32_t a = SW128((wid * 16 + lrow) * 128 + kk * 32 + lhalf * 16);
        LDSM4(qfh[kk], sb + a);
        LDSM4(qfl[kk], sb + 16384 + a);
    }

    float o[8][4];
#pragma unroll
    for (int nf = 0; nf < 8; nf++)
#pragma unroll
        for (int e = 0; e < 4; e++) o[nf][e] = 0.f;
    float m0 = -1e30f, m1 = -1e30f, l0 = 0.f, l1 = 0.f;

    const int qloc0 = wid * 16 + (lane >> 2);   // local q row of frag half 0

    for (int it = 0; it < ntiles; it++) {
        if (it > 0) { CP_WAIT1(); __syncthreads(); }
        const int buf = it & 1;
        const int kt = it * 64;
        const uint32_t tK = sb + 32768 + buf * 32768;          // kh; kl=+8192
        const uint32_t tV = tK + 16384;                        // vh; vl=+8192

        // ---- scores ----
        float s[8][4];
#pragma unroll
        for (int nf = 0; nf < 8; nf++)
#pragma unroll
            for (int e = 0; e < 4; e++) s[nf][e] = 0.f;

#pragma unroll
        for (int kk = 0; kk < 4; kk++) {
            const int kb = kk * 32 + lhalf * 16;
            uint32_t kh4[4][4], kl4[4][4];
#pragma unroll
            for (int n16 = 0; n16 < 4; n16++) {
                uint32_t a = SW128((n16 * 16 + lrow) * 128 + kb);
                LDSM4(kh4[n16], tK + a);
                LDSM4(kl4[n16], tK + 8192 + a);
            }
#pragma unroll
            for (int nf = 0; nf < 8; nf++) {
                const int n16 = nf >> 1, od = nf & 1;
                MMA16816(s[nf], qfh[kk], kh4[n16][od], kh4[n16][od + 2]);
                MMA16816(s[nf], qfl[kk], kh4[n16][od], kh4[n16][od + 2]);
                MMA16816(s[nf], qfh[kk], kl4[n16][od], kl4[n16][od + 2]);
            }
        }

        // ---- causal mask (last two tiles only) ----
        if (kt + 63 > diag0) {
            const int lim0 = diag0 - kt + qloc0;       // allowed col <= lim
#pragma unroll
            for (int nf = 0; nf < 8; nf++) {
                int c0 = nf * 8 + (lane & 3) * 2;
                if (c0 > lim0)     s[nf][0] = -1e30f;
                if (c0 + 1 > lim0) s[nf][1] = -1e30f;
                if (c0 > lim0 + 8)     s[nf][2] = -1e30f;
                if (c0 + 1 > lim0 + 8) s[nf][3] = -1e30f;
            }
        }

        // ---- online softmax ----
        float mx0 = -1e30f, mx1 = -1e30f;
#pragma unroll
        for (int nf = 0; nf < 8; nf++) {
            mx0 = fmaxf(mx0, fmaxf(s[nf][0], s[nf][1]));
            mx1 = fmaxf(mx1, fmaxf(s[nf][2], s[nf][3]));
        }
        mx0 = fmaxf(mx0, __shfl_xor_sync(0xffffffffu, mx0, 1));
        mx0 = fmaxf(mx0, __shfl_xor_sync(0xffffffffu, mx0, 2));
        mx1 = fmaxf(mx1, __shfl_xor_sync(0xffffffffu, mx1, 1));
        mx1 = fmaxf(mx1, __shfl_xor_sync(0xffffffffu, mx1, 2));
        const float mn0 = fmaxf(m0, mx0), mn1 = fmaxf(m1, mx1);
        const float a0 = __expf(m0 - mn0), a1 = __expf(m1 - mn1);
        m0 = mn0; m1 = mn1;
        float sm0 = 0.f, sm1 = 0.f;
#pragma unroll
        for (int nf = 0; nf < 8; nf++) {
            s[nf][0] = __expf(s[nf][0] - mn0);
            s[nf][1] = __expf(s[nf][1] - mn0);
            s[nf][2] = __expf(s[nf][2] - mn1);
            s[nf][3] = __expf(s[nf][3] - mn1);
            sm0 += s[nf][0] + s[nf][1];
            sm1 += s[nf][2] + s[nf][3];
        }
        sm0 += __shfl_xor_sync(0xffffffffu, sm0, 1);
        sm0 += __shfl_xor_sync(0xffffffffu, sm0, 2);
        sm1 += __shfl_xor_sync(0xffffffffu, sm1, 1);
        sm1 += __shfl_xor_sync(0xffffffffu, sm1, 2);
        l0 = l0 * a0 + sm0;
        l1 = l1 * a1 + sm1;
#pragma unroll
        for (int nf = 0; nf < 8; nf++) {
            o[nf][0] *= a0; o[nf][1] *= a0;
            o[nf][2] *= a1; o[nf][3] *= a1;
        }

        // ---- pack P (c-frag -> A-frag, hi/lo) ----
        uint32_t ph[4][4], pl[4][4];
#pragma unroll
        for (int kk = 0; kk < 4; kk++) {
            packhl(s[2 * kk][0],     s[2 * kk][1],     ph[kk][0], pl[kk][0]);
            packhl(s[2 * kk][2],     s[2 * kk][3],     ph[kk][1], pl[kk][1]);
            packhl(s[2 * kk + 1][0], s[2 * kk + 1][1], ph[kk][2], pl[kk][2]);
            packhl(s[2 * kk + 1][2], s[2 * kk + 1][3], ph[kk][3], pl[kk][3]);
        }

        // ---- PV ----
#pragma unroll
        for (int kk = 0; kk < 4; kk++) {
#pragma unroll
            for (int dn = 0; dn < 4; dn++) {
                uint32_t a = SW128((kk * 16 + lrow) * 128 + dn * 32 + lhalf * 16);
                uint32_t vh4[4], vl4[4];
                LDSM4T(vh4, tV + a);
                LDSM4T(vl4, tV + 8192 + a);
#pragma unroll
                for (int od = 0; od < 2; od++) {
                    const int nf = dn * 2 + od;
                    MMA16816(o[nf], ph[kk], vh4[od * 2], vh4[od * 2 + 1]);
                    MMA16816(o[nf], pl[kk], vh4[od * 2], vh4[od * 2 + 1]);
                    MMA16816(o[nf], ph[kk], vl4[od * 2], vl4[od * 2 + 1]);
                }
            }
        }

        __syncthreads();
        if (it + 2 < ntiles) copy_kv(buf, it + 2);
        CP_COMMIT();
    }

    // ---- epilogue ----
    const float i0 = 1.f / l0, i1 = 1.f / l1;
    const int qrow = qt * 128 + qloc0;
    float* op = attn_out + (size_t)(b * Ssz + qrow) * Ez + h * 64 + (lane & 3) * 2;
#pragma unroll
    for (int nf = 0; nf < 8; nf++) {
        float2 v0 = { o[nf][0] * i0, o[nf][1] * i0 };
        float2 v1 = { o[nf][2] * i1, o[nf][3] * i1 };
        *(float2*)(op + nf * 8) = v0;
        *(float2*)(op + 8 * (size_t)Ez + nf * 8) = v1;
    }
}

// ---------------------------------------------------------------------------
extern "C" void kernel_launch(void* const* d_in, const int* in_sizes, int n_in,
                              void* d_out, int out_size)
{
    const float* x      = (const float*)d_in[0];
    const float* past   = (const float*)d_in[1];
    const float* w_attn = (const float*)d_in[2];
    const float* b_attn = (const float*)d_in[3];
    const float* w_proj = (const float*)d_in[4];
    const float* b_proj = (const float*)d_in[5];
    float* out = (float*)d_out;
    float* present = out + (size_t)Mz * Ez;

    float *qkv, *attn;
    __nv_bfloat16 *ah, *al, *wah, *wal, *wph, *wpl, *qh, *ql, *kh, *kl, *vh, *vl;
    cudaGetSymbolAddress((void**)&qkv,  g_qkv);
    cudaGetSymbolAddress((void**)&attn, g_attn);
    cudaGetSymbolAddress((void**)&ah,  g_ah);
    cudaGetSymbolAddress((void**)&al,  g_al);
    cudaGetSymbolAddress((void**)&wah, g_wah);
    cudaGetSymbolAddress((void**)&wal, g_wal);
    cudaGetSymbolAddress((void**)&wph, g_wph);
    cudaGetSymbolAddress((void**)&wpl, g_wpl);
    cudaGetSymbolAddress((void**)&qh, g_qh);
    cudaGetSymbolAddress((void**)&ql, g_ql);
    cudaGetSymbolAddress((void**)&kh, g_kh);
    cudaGetSymbolAddress((void**)&kl, g_kl);
    cudaGetSymbolAddress((void**)&vh, g_vh);
    cudaGetSymbolAddress((void**)&vl, g_vl);

    static const int SMEM_GEMM = 2 * 4 * 16384;        // 131072
    static const int SMEM_ATTN = 32768 + 2 * 32768;    // 98304
    cudaFuncSetAttribute(gemm_mma, cudaFuncAttributeMaxDynamicSharedMemorySize, SMEM_GEMM);
    cudaFuncSetAttribute(attn_mma, cudaFuncAttributeMaxDynamicSharedMemorySize, SMEM_ATTN);

    const size_t kvcount = (size_t)Bz * Hz * NSz * Dz;   // 8.39M (per K or V)

    // 0) weight transpose+split
    splitT<<<dim3(E3 / 32, Ez / 32), dim3(32, 8)>>>(w_attn, wah, wal, Ez, E3);
    splitT<<<dim3(Ez / 32, Ez / 32), dim3(32, 8)>>>(w_proj, wph, wpl, Ez, Ez);
    // 1) split x
    split_hl<<<(Mz * Ez) / 1024, 256>>>(x, ah, al);
    // 2) qkv = x @ w_attn + b_attn  (HMMA)
    gemm_mma<<<dim3(E3 / 128, Mz / 128), 256, SMEM_GEMM>>>(ah, al, wah, wal,
                                                           b_attn, qkv, E3, Ez);
    // 3) present
    build_present<<<16384, 256>>>(past, qkv, present);
    // 4) split K/V/Q for attention
    split_hl<<<(int)(kvcount / 1024), 256>>>(present, kh, kl);
    split_hl<<<(int)(kvcount / 1024), 256>>>(present + kvcount, vh, vl);
    split_q<<<(int)((size_t)Bz * Hz * Ssz * Dz / 1024), 256>>>(qkv, qh, ql);
    // 5) attention (HMMA flash)
    attn_mma<<<dim3(Ssz / 128, Hz, Bz), 256, SMEM_ATTN>>>(qh, ql, kh, kl, vh, vl, attn);
    // 6) split attn
    split_hl<<<(Mz * Ez) / 1024, 256>>>(attn, ah, al);
    // 7) out = attn @ w_proj + b_proj  (HMMA)
    gemm_mma<<<dim3(Ez / 128, Mz / 128), 256, SMEM_GEMM>>>(ah, al, wph, wpl,
                                                           b_proj, out, Ez, Ez);
}

// round 8
// speedup vs baseline: 4.7249x; 1.0399x over previous
#include <cuda_runtime.h>
#include <cuda_bf16.h>
#include <cstdint>
#include <cstddef>

#define Bz   4
#define Ssz  1024
#define Pz   1024
#define Ez   1024
#define Hz   16
#define Dz   64
#define NSz  2048
#define Mz   4096
#define E3   3072

// ---------------- scratch ---------------------------------------------------
__device__ __align__(16) __nv_bfloat16 g_ah[(size_t)Mz * Ez];
__device__ __align__(16) __nv_bfloat16 g_al[(size_t)Mz * Ez];
__device__ __align__(16) __nv_bfloat16 g_wah[(size_t)E3 * Ez];
__device__ __align__(16) __nv_bfloat16 g_wal[(size_t)E3 * Ez];
__device__ __align__(16) __nv_bfloat16 g_wph[(size_t)Ez * Ez];
__device__ __align__(16) __nv_bfloat16 g_wpl[(size_t)Ez * Ez];
__device__ __align__(16) __nv_bfloat16 g_qh[(size_t)Bz * Hz * Ssz * Dz];
__device__ __align__(16) __nv_bfloat16 g_ql[(size_t)Bz * Hz * Ssz * Dz];
__device__ __align__(16) __nv_bfloat16 g_kh[(size_t)Bz * Hz * NSz * Dz];
__device__ __align__(16) __nv_bfloat16 g_kl[(size_t)Bz * Hz * NSz * Dz];
__device__ __align__(16) __nv_bfloat16 g_vh[(size_t)Bz * Hz * NSz * Dz];
__device__ __align__(16) __nv_bfloat16 g_vl[(size_t)Bz * Hz * NSz * Dz];

// ---------------- PTX helpers ----------------------------------------------
__device__ __forceinline__ uint32_t smem_u32(const void* p) {
    uint32_t a;
    asm("{ .reg .u64 t; cvta.to.shared.u64 t, %1; cvt.u32.u64 %0, t; }"
        : "=r"(a) : "l"(p));
    return a;
}
#define CP_ASYNC16(dst, src) \
    asm volatile("cp.async.cg.shared.global [%0], [%1], 16;" \
                 :: "r"(dst), "l"(src) : "memory")
#define CP_COMMIT() asm volatile("cp.async.commit_group;" ::: "memory")
#define CP_WAIT1()  asm volatile("cp.async.wait_group 1;" ::: "memory")

#define LDSM4(r, a) \
    asm volatile("ldmatrix.sync.aligned.m8n8.x4.shared.b16 {%0,%1,%2,%3}, [%4];" \
                 : "=r"((r)[0]), "=r"((r)[1]), "=r"((r)[2]), "=r"((r)[3]) : "r"(a))
#define LDSM4T(r, a) \
    asm volatile("ldmatrix.sync.aligned.m8n8.x4.trans.shared.b16 {%0,%1,%2,%3}, [%4];" \
                 : "=r"((r)[0]), "=r"((r)[1]), "=r"((r)[2]), "=r"((r)[3]) : "r"(a))

#define MMA16816(c, a, b0, b1) \
    asm volatile("mma.sync.aligned.m16n8k16.row.col.f32.bf16.bf16.f32 " \
                 "{%0,%1,%2,%3},{%4,%5,%6,%7},{%8,%9},{%0,%1,%2,%3};" \
                 : "+f"((c)[0]), "+f"((c)[1]), "+f"((c)[2]), "+f"((c)[3]) \
                 : "r"((a)[0]), "r"((a)[1]), "r"((a)[2]), "r"((a)[3]), \
                   "r"(b0), "r"(b1))

#define SW128(o) ((o) ^ (((o) >> 3) & 0x70))

__device__ __forceinline__ void packhl(float f0, float f1, uint32_t& h, uint32_t& l) {
    __nv_bfloat16 h0 = __float2bfloat16(f0), h1 = __float2bfloat16(f1);
    __nv_bfloat16 l0 = __float2bfloat16(f0 - __bfloat162float(h0));
    __nv_bfloat16 l1 = __float2bfloat16(f1 - __bfloat162float(h1));
    __nv_bfloat162 hv(h0, h1), lv(l0, l1);
    h = *(uint32_t*)&hv;
    l = *(uint32_t*)&lv;
}

// ---------------------------------------------------------------------------
// Split fp32 -> bf16 hi + lo (used for input x only)
// ---------------------------------------------------------------------------
__global__ __launch_bounds__(256) void split_hl(
    const float* __restrict__ src, __nv_bfloat16* __restrict__ hi,
    __nv_bfloat16* __restrict__ lo)
{
    size_t i = (size_t)blockIdx.x * 256 + threadIdx.x;
    float4 v = ((const float4*)src)[i];
    uint32_t h0, l0, h1, l1;
    packhl(v.x, v.y, h0, l0);
    packhl(v.z, v.w, h1, l1);
    ((uint32_t*)hi)[2 * i]     = h0;
    ((uint32_t*)hi)[2 * i + 1] = h1;
    ((uint32_t*)lo)[2 * i]     = l0;
    ((uint32_t*)lo)[2 * i + 1] = l1;
}

// ---------------------------------------------------------------------------
// past -> present[.., 0:P, ..] (fp32 copy) + kh/kl/vh/vl splits for t<P
// ---------------------------------------------------------------------------
__global__ __launch_bounds__(256) void past_split(
    const float* __restrict__ past, float* __restrict__ present,
    __nv_bfloat16* __restrict__ kh, __nv_bfloat16* __restrict__ kl,
    __nv_bfloat16* __restrict__ vh, __nv_bfloat16* __restrict__ vl)
{
    size_t i4 = (size_t)blockIdx.x * 256 + threadIdx.x;   // over [2,B,H,P,D]/4
    size_t e = i4 * 4;
    int d = (int)(e & 63);
    size_t r = e >> 6;
    int t = (int)(r % Pz); r /= Pz;
    int h = (int)(r % Hz); r /= Hz;
    int b = (int)(r % Bz);
    int c = (int)(r / Bz);
    float4 v = *(const float4*)(past + e);
    // present index: ((((c*Bz)+b)*Hz+h)*NSz + t)*Dz + d
    size_t pidx = ((((size_t)c * Bz + b) * Hz + h) * NSz + t) * Dz + d;
    *(float4*)(present + pidx) = v;
    uint32_t h0, l0, h1, l1;
    packhl(v.x, v.y, h0, l0);
    packhl(v.z, v.w, h1, l1);
    size_t sidx = (((size_t)(b * Hz + h)) * NSz + t) * Dz + d;   // bf16 elem idx
    __nv_bfloat16* hp = (c == 0) ? kh : vh;
    __nv_bfloat16* lp = (c == 0) ? kl : vl;
    *(uint32_t*)(hp + sidx)     = h0;
    *(uint32_t*)(hp + sidx + 2) = h1;
    *(uint32_t*)(lp + sidx)     = l0;
    *(uint32_t*)(lp + sidx + 2) = l1;
}

// ---------------------------------------------------------------------------
// Transpose + split weights: src [K,N] f32 -> hi/lo [N,K] bf16
// ---------------------------------------------------------------------------
__global__ __launch_bounds__(256) void splitT(
    const float* __restrict__ src, __nv_bfloat16* __restrict__ hi,
    __nv_bfloat16* __restrict__ lo, int K, int N)
{
    __shared__ float t[32][33];
    int n0 = blockIdx.x * 32, k0 = blockIdx.y * 32;
    int tx = threadIdx.x, ty = threadIdx.y;
#pragma unroll
    for (int i = 0; i < 32; i += 8)
        t[ty + i][tx] = src[(size_t)(k0 + ty + i) * N + (n0 + tx)];
    __syncthreads();
#pragma unroll
    for (int i = 0; i < 32; i += 8) {
        int n = n0 + ty + i, k = k0 + tx;
        float v = t[tx][ty + i];
        __nv_bfloat16 h = __float2bfloat16(v);
        hi[(size_t)n * K + k] = h;
        lo[(size_t)n * K + k] = __float2bfloat16(v - __bfloat162float(h));
    }
}

// ---------------------------------------------------------------------------
// Shared GEMM mainloop (BK=64, double buffer) producing c[2][8][4].
// ---------------------------------------------------------------------------
struct GemmCore {
    float c[2][8][4];
};

__device__ __forceinline__ void gemm_mainloop(
    GemmCore& G, uint32_t sb, int tid, int wid, int lane,
    const char* gA0, const char* gA1, const char* gB0, const char* gB1,
    int Kb, int nck)
{
    const int wm = wid & 3, wn = wid >> 2;
    const char* gA[2] = { gA0, gA1 };
    const char* gB[2] = { gB0, gB1 };

    auto copy_stage = [&](int buf, int ck) {
        const int koff = ck * 128;
#pragma unroll
        for (int t = 0; t < 4; t++) {
            const char* g = (t < 2 ? gA[t] : gB[t - 2]) + koff;
            uint32_t s = sb + ((buf << 2) + t) * 16384;
#pragma unroll
            for (int j = 0; j < 4; j++) {
                int i = tid + 256 * j;
                int rr = i >> 3, cc = (i & 7) << 4;
                CP_ASYNC16(s + SW128(rr * 128 + cc), g + (size_t)rr * Kb + cc);
            }
        }
    };

    copy_stage(0, 0); CP_COMMIT();
    if (nck > 1) copy_stage(1, 1);
    CP_COMMIT();

#pragma unroll
    for (int mf = 0; mf < 2; mf++)
#pragma unroll
        for (int nf = 0; nf < 8; nf++)
#pragma unroll
            for (int k = 0; k < 4; k++) G.c[mf][nf][k] = 0.f;

    const int lrow = lane & 15, lhalf = lane >> 4;

    for (int ck = 0; ck < nck; ck++) {
        CP_WAIT1();
        __syncthreads();
        const int buf = ck & 1;
        const uint32_t tAh = sb + ((buf << 2) + 0) * 16384;
        const uint32_t tAl = sb + ((buf << 2) + 1) * 16384;
        const uint32_t tBh = sb + ((buf << 2) + 2) * 16384;
        const uint32_t tBl = sb + ((buf << 2) + 3) * 16384;

#pragma unroll
        for (int k16 = 0; k16 < 4; k16++) {
            const int kb = k16 * 32 + lhalf * 16;
            uint32_t ah[2][4], al[2][4], bh[4][4], bl[4][4];
#pragma unroll
            for (int mf = 0; mf < 2; mf++) {
                int row = wm * 32 + mf * 16 + lrow;
                LDSM4(ah[mf], tAh + SW128(row * 128 + kb));
                LDSM4(al[mf], tAl + SW128(row * 128 + kb));
            }
#pragma unroll
            for (int bp = 0; bp < 4; bp++) {
                int row = wn * 64 + bp * 16 + lrow;
                LDSM4(bh[bp], tBh + SW128(row * 128 + kb));
                LDSM4(bl[bp], tBl + SW128(row * 128 + kb));
            }
#pragma unroll
            for (int mf = 0; mf < 2; mf++)
#pragma unroll
                for (int nf = 0; nf < 8; nf++) {
                    const int bp = nf >> 1, od = nf & 1;
                    MMA16816(G.c[mf][nf], ah[mf], bh[bp][od], bh[bp][od + 2]);
                    MMA16816(G.c[mf][nf], al[mf], bh[bp][od], bh[bp][od + 2]);
                    MMA16816(G.c[mf][nf], ah[mf], bl[bp][od], bl[bp][od + 2]);
                }
        }
        __syncthreads();
        if (ck + 2 < nck) copy_stage(buf, ck + 2);
        CP_COMMIT();
    }
}

// ---------------------------------------------------------------------------
// QKV GEMM with fused routing epilogue.
// q cols: *0.125, split -> qh/ql  [B,H,S,D]
// k cols: fp32 -> present[0], split -> kh/kl at t=P+s
// v cols: fp32 -> present[1], split -> vh/vl
// ---------------------------------------------------------------------------
__global__ __launch_bounds__(256) void gemm_qkv(
    const __nv_bfloat16* __restrict__ Ah, const __nv_bfloat16* __restrict__ Al,
    const __nv_bfloat16* __restrict__ Bh, const __nv_bfloat16* __restrict__ Bl,
    const float* __restrict__ bias, float* __restrict__ present,
    __nv_bfloat16* __restrict__ qh, __nv_bfloat16* __restrict__ ql,
    __nv_bfloat16* __restrict__ kh, __nv_bfloat16* __restrict__ kl,
    __nv_bfloat16* __restrict__ vh, __nv_bfloat16* __restrict__ vl)
{
    extern __shared__ __align__(1024) char smem[];
    const uint32_t sb = smem_u32(smem);
    const int tid = threadIdx.x, wid = tid >> 5, lane = tid & 31;
    const int bn = blockIdx.x, bm = blockIdx.y;
    const int K = Ez, Kb = K * 2;

    GemmCore G;
    gemm_mainloop(G, sb, tid, wid, lane,
                  (const char*)(Ah + (size_t)(bm * 128) * K),
                  (const char*)(Al + (size_t)(bm * 128) * K),
                  (const char*)(Bh + (size_t)(bn * 128) * K),
                  (const char*)(Bl + (size_t)(bn * 128) * K),
                  Kb, K >> 6);

    const int wm = wid & 3, wn = wid >> 2;
    const int colbase = bn * 128 + wn * 64;      // 64-aligned -> single (sec,h)
    const int sec = colbase >> 10;               // 0=q 1=k 2=v
    const int hh = (colbase & 1023) >> 6;
    const int d0 = (lane & 3) * 2;
    const int r0 = bm * 128 + wm * 32 + (lane >> 2);

#pragma unroll
    for (int mf = 0; mf < 2; mf++) {
#pragma unroll
        for (int half = 0; half < 2; half++) {
            const int r = r0 + mf * 16 + half * 8;
            const int b = r >> 10, s = r & 1023;
            const int e0 = half * 2;            // c[..][e0], c[..][e0+1]
#pragma unroll
            for (int nf = 0; nf < 8; nf++) {
                const int d = d0 + nf * 8;
                float vx = G.c[mf][nf][e0]     + bias[sec * 1024 + hh * 64 + d];
                float vy = G.c[mf][nf][e0 + 1] + bias[sec * 1024 + hh * 64 + d + 1];
                if (sec == 0) {
                    uint32_t ph, pl;
                    packhl(vx * 0.125f, vy * 0.125f, ph, pl);
                    size_t idx = (((size_t)(b * Hz + hh)) * Ssz + s) * Dz + d;
                    *(uint32_t*)(qh + idx) = ph;
                    *(uint32_t*)(ql + idx) = pl;
                } else {
                    size_t t = (size_t)Pz + s;
                    size_t pidx = ((((size_t)(sec - 1) * Bz + b) * Hz + hh) * NSz + t) * Dz + d;
                    float2 pv = { vx, vy };
                    *(float2*)(present + pidx) = pv;
                    uint32_t ph, pl;
                    packhl(vx, vy, ph, pl);
                    size_t sidx = (((size_t)(b * Hz + hh)) * NSz + t) * Dz + d;
                    if (sec == 1) {
                        *(uint32_t*)(kh + sidx) = ph;
                        *(uint32_t*)(kl + sidx) = pl;
                    } else {
                        *(uint32_t*)(vh + sidx) = ph;
                        *(uint32_t*)(vl + sidx) = pl;
                    }
                }
            }
        }
    }
}

// ---------------------------------------------------------------------------
// proj GEMM: fp32 C + bias (unchanged epilogue)
// ---------------------------------------------------------------------------
__global__ __launch_bounds__(256) void gemm_mma(
    const __nv_bfloat16* __restrict__ Ah, const __nv_bfloat16* __restrict__ Al,
    const __nv_bfloat16* __restrict__ Bh, const __nv_bfloat16* __restrict__ Bl,
    const float* __restrict__ bias, float* __restrict__ C, int N, int K)
{
    extern __shared__ __align__(1024) char smem[];
    const uint32_t sb = smem_u32(smem);
    const int tid = threadIdx.x, wid = tid >> 5, lane = tid & 31;
    const int bn = blockIdx.x, bm = blockIdx.y;

    GemmCore G;
    gemm_mainloop(G, sb, tid, wid, lane,
                  (const char*)(Ah + (size_t)(bm * 128) * K),
                  (const char*)(Al + (size_t)(bm * 128) * K),
                  (const char*)(Bh + (size_t)(bn * 128) * K),
                  (const char*)(Bl + (size_t)(bn * 128) * K),
                  K * 2, K >> 6);

    const int wm = wid & 3, wn = wid >> 2;
    const int crow = bm * 128 + wm * 32 + (lane >> 2);
    const int ccol = bn * 128 + wn * 64 + (lane & 3) * 2;
    const float* bp = bias + ccol;
#pragma unroll
    for (int mf = 0; mf < 2; mf++) {
#pragma unroll
        for (int nf = 0; nf < 8; nf++) {
            float2 bv = *(const float2*)(bp + nf * 8);
            float2 v0 = { G.c[mf][nf][0] + bv.x, G.c[mf][nf][1] + bv.y };
            float2 v1 = { G.c[mf][nf][2] + bv.x, G.c[mf][nf][3] + bv.y };
            size_t r0i = (size_t)(crow + mf * 16) * N + ccol + nf * 8;
            *(float2*)(C + r0i) = v0;
            *(float2*)(C + r0i + 8 * (size_t)N) = v1;
        }
    }
}

// ---------------------------------------------------------------------------
// HMMA flash attention; epilogue writes bf16 hi/lo (ah/al) directly.
// ---------------------------------------------------------------------------
__global__ __launch_bounds__(256) void attn_mma(
    const __nv_bfloat16* __restrict__ qh_g, const __nv_bfloat16* __restrict__ ql_g,
    const __nv_bfloat16* __restrict__ kh_g, const __nv_bfloat16* __restrict__ kl_g,
    const __nv_bfloat16* __restrict__ vh_g, const __nv_bfloat16* __restrict__ vl_g,
    __nv_bfloat16* __restrict__ oh, __nv_bfloat16* __restrict__ ol)
{
    extern __shared__ __align__(1024) char smem[];
    const uint32_t sb = smem_u32(smem);
    const int tid = threadIdx.x, wid = tid >> 5, lane = tid & 31;
    const int qt = blockIdx.x, h = blockIdx.y, b = blockIdx.z;
    const int lrow = lane & 15, lhalf = lane >> 4;

    const size_t bh = (size_t)(b * Hz + h);
    const char* qhg = (const char*)(qh_g + (bh * Ssz + (size_t)qt * 128) * Dz);
    const char* qlg = (const char*)(ql_g + (bh * Ssz + (size_t)qt * 128) * Dz);
    const char* kvg[4] = { (const char*)(kh_g + bh * NSz * Dz),
                           (const char*)(kl_g + bh * NSz * Dz),
                           (const char*)(vh_g + bh * NSz * Dz),
                           (const char*)(vl_g + bh * NSz * Dz) };

    const int diag0 = Pz + qt * 128;
    const int ntiles = (diag0 + 128) >> 6;

    auto copy_kv = [&](int buf, int t) {
        const size_t off = (size_t)t * 64 * 128;
#pragma unroll
        for (int p = 0; p < 4; p++) {
            uint32_t s = sb + 32768 + buf * 32768 + p * 8192;
            const char* g = kvg[p] + off;
#pragma unroll
            for (int j = 0; j < 2; j++) {
                int i = tid + 256 * j;
                int r = i >> 3, c = (i & 7) << 4;
                CP_ASYNC16(s + SW128(r * 128 + c), g + r * 128 + c);
            }
        }
    };

#pragma unroll
    for (int j = 0; j < 4; j++) {
        int i = tid + 256 * j;
        int r = i >> 3, c = (i & 7) << 4;
        CP_ASYNC16(sb + SW128(r * 128 + c), qhg + r * 128 + c);
        CP_ASYNC16(sb + 16384 + SW128(r * 128 + c), qlg + r * 128 + c);
    }
    copy_kv(0, 0); CP_COMMIT();
    copy_kv(1, 1); CP_COMMIT();

    CP_WAIT1();
    __syncthreads();

    uint32_t qfh[4][4], qfl[4][4];
#pragma unroll
    for (int kk = 0; kk < 4; kk++) {
        uint32_t a = SW128((wid * 16 + lrow) * 128 + kk * 32 + lhalf * 16);
        LDSM4(qfh[kk], sb + a);
        LDSM4(qfl[kk], sb + 16384 + a);
    }

    float o[8][4];
#pragma unroll
    for (int nf = 0; nf < 8; nf++)
#pragma unroll
        for (int e = 0; e < 4; e++) o[nf][e] = 0.f;
    float m0 = -1e30f, m1 = -1e30f, l0 = 0.f, l1 = 0.f;

    const int qloc0 = wid * 16 + (lane >> 2);

    for (int it = 0; it < ntiles; it++) {
        if (it > 0) { CP_WAIT1(); __syncthreads(); }
        const int buf = it & 1;
        const int kt = it * 64;
        const uint32_t tK = sb + 32768 + buf * 32768;
        const uint32_t tV = tK + 16384;

        float s[8][4];
#pragma unroll
        for (int nf = 0; nf < 8; nf++)
#pragma unroll
            for (int e = 0; e < 4; e++) s[nf][e] = 0.f;

#pragma unroll
        for (int kk = 0; kk < 4; kk++) {
            const int kb = kk * 32 + lhalf * 16;
            uint32_t kh4[4][4], kl4[4][4];
#pragma unroll
            for (int n16 = 0; n16 < 4; n16++) {
                uint32_t a = SW128((n16 * 16 + lrow) * 128 + kb);
                LDSM4(kh4[n16], tK + a);
                LDSM4(kl4[n16], tK + 8192 + a);
            }
#pragma unroll
            for (int nf = 0; nf < 8; nf++) {
                const int n16 = nf >> 1, od = nf & 1;
                MMA16816(s[nf], qfh[kk], kh4[n16][od], kh4[n16][od + 2]);
                MMA16816(s[nf], qfl[kk], kh4[n16][od], kh4[n16][od + 2]);
                MMA16816(s[nf], qfh[kk], kl4[n16][od], kl4[n16][od + 2]);
            }
        }

        if (kt + 63 > diag0) {
            const int lim0 = diag0 - kt + qloc0;
#pragma unroll
            for (int nf = 0; nf < 8; nf++) {
                int c0 = nf * 8 + (lane & 3) * 2;
                if (c0 > lim0)     s[nf][0] = -1e30f;
                if (c0 + 1 > lim0) s[nf][1] = -1e30f;
                if (c0 > lim0 + 8)     s[nf][2] = -1e30f;
                if (c0 + 1 > lim0 + 8) s[nf][3] = -1e30f;
            }
        }

        float mx0 = -1e30f, mx1 = -1e30f;
#pragma unroll
        for (int nf = 0; nf < 8; nf++) {
            mx0 = fmaxf(mx0, fmaxf(s[nf][0], s[nf][1]));
            mx1 = fmaxf(mx1, fmaxf(s[nf][2], s[nf][3]));
        }
        mx0 = fmaxf(mx0, __shfl_xor_sync(0xffffffffu, mx0, 1));
        mx0 = fmaxf(mx0, __shfl_xor_sync(0xffffffffu, mx0, 2));
        mx1 = fmaxf(mx1, __shfl_xor_sync(0xffffffffu, mx1, 1));
        mx1 = fmaxf(mx1, __shfl_xor_sync(0xffffffffu, mx1, 2));
        const float mn0 = fmaxf(m0, mx0), mn1 = fmaxf(m1, mx1);
        const float a0 = __expf(m0 - mn0), a1 = __expf(m1 - mn1);
        m0 = mn0; m1 = mn1;
        float sm0 = 0.f, sm1 = 0.f;
#pragma unroll
        for (int nf = 0; nf < 8; nf++) {
            s[nf][0] = __expf(s[nf][0] - mn0);
            s[nf][1] = __expf(s[nf][1] - mn0);
            s[nf][2] = __expf(s[nf][2] - mn1);
            s[nf][3] = __expf(s[nf][3] - mn1);
            sm0 += s[nf][0] + s[nf][1];
            sm1 += s[nf][2] + s[nf][3];
        }
        sm0 += __shfl_xor_sync(0xffffffffu, sm0, 1);
        sm0 += __shfl_xor_sync(0xffffffffu, sm0, 2);
        sm1 += __shfl_xor_sync(0xffffffffu, sm1, 1);
        sm1 += __shfl_xor_sync(0xffffffffu, sm1, 2);
        l0 = l0 * a0 + sm0;
        l1 = l1 * a1 + sm1;
#pragma unroll
        for (int nf = 0; nf < 8; nf++) {
            o[nf][0] *= a0; o[nf][1] *= a0;
            o[nf][2] *= a1; o[nf][3] *= a1;
        }

        uint32_t ph[4][4], pl[4][4];
#pragma unroll
        for (int kk = 0; kk < 4; kk++) {
            packhl(s[2 * kk][0],     s[2 * kk][1],     ph[kk][0], pl[kk][0]);
            packhl(s[2 * kk][2],     s[2 * kk][3],     ph[kk][1], pl[kk][1]);
            packhl(s[2 * kk + 1][0], s[2 * kk + 1][1], ph[kk][2], pl[kk][2]);
            packhl(s[2 * kk + 1][2], s[2 * kk + 1][3], ph[kk][3], pl[kk][3]);
        }

#pragma unroll
        for (int kk = 0; kk < 4; kk++) {
#pragma unroll
            for (int dn = 0; dn < 4; dn++) {
                uint32_t a = SW128((kk * 16 + lrow) * 128 + dn * 32 + lhalf * 16);
                uint32_t vh4[4], vl4[4];
                LDSM4T(vh4, tV + a);
                LDSM4T(vl4, tV + 8192 + a);
#pragma unroll
                for (int od = 0; od < 2; od++) {
                    const int nf = dn * 2 + od;
                    MMA16816(o[nf], ph[kk], vh4[od * 2], vh4[od * 2 + 1]);
                    MMA16816(o[nf], pl[kk], vh4[od * 2], vh4[od * 2 + 1]);
                    MMA16816(o[nf], ph[kk], vl4[od * 2], vl4[od * 2 + 1]);
                }
            }
        }

        __syncthreads();
        if (it + 2 < ntiles) copy_kv(buf, it + 2);
        CP_COMMIT();
    }

    // epilogue: normalize, pack hi/lo, write ah/al at [b*S+qrow][h*64+d]
    const float i0 = 1.f / l0, i1 = 1.f / l1;
    const int qrow = qt * 128 + qloc0;
    const size_t base0 = (size_t)(b * Ssz + qrow) * Ez + h * 64 + (lane & 3) * 2;
    const size_t base1 = base0 + 8 * (size_t)Ez;
#pragma unroll
    for (int nf = 0; nf < 8; nf++) {
        uint32_t ph0, pl0, ph1, pl1;
        packhl(o[nf][0] * i0, o[nf][1] * i0, ph0, pl0);
        packhl(o[nf][2] * i1, o[nf][3] * i1, ph1, pl1);
        *(uint32_t*)(oh + base0 + nf * 8) = ph0;
        *(uint32_t*)(ol + base0 + nf * 8) = pl0;
        *(uint32_t*)(oh + base1 + nf * 8) = ph1;
        *(uint32_t*)(ol + base1 + nf * 8) = pl1;
    }
}

// ---------------------------------------------------------------------------
extern "C" void kernel_launch(void* const* d_in, const int* in_sizes, int n_in,
                              void* d_out, int out_size)
{
    const float* x      = (const float*)d_in[0];
    const float* past   = (const float*)d_in[1];
    const float* w_attn = (const float*)d_in[2];
    const float* b_attn = (const float*)d_in[3];
    const float* w_proj = (const float*)d_in[4];
    const float* b_proj = (const float*)d_in[5];
    float* out = (float*)d_out;
    float* present = out + (size_t)Mz * Ez;

    __nv_bfloat16 *ah, *al, *wah, *wal, *wph, *wpl, *qh, *ql, *kh, *kl, *vh, *vl;
    cudaGetSymbolAddress((void**)&ah,  g_ah);
    cudaGetSymbolAddress((void**)&al,  g_al);
    cudaGetSymbolAddress((void**)&wah, g_wah);
    cudaGetSymbolAddress((void**)&wal, g_wal);
    cudaGetSymbolAddress((void**)&wph, g_wph);
    cudaGetSymbolAddress((void**)&wpl, g_wpl);
    cudaGetSymbolAddress((void**)&qh, g_qh);
    cudaGetSymbolAddress((void**)&ql, g_ql);
    cudaGetSymbolAddress((void**)&kh, g_kh);
    cudaGetSymbolAddress((void**)&kl, g_kl);
    cudaGetSymbolAddress((void**)&vh, g_vh);
    cudaGetSymbolAddress((void**)&vl, g_vl);

    static const int SMEM_GEMM = 2 * 4 * 16384;        // 131072
    static const int SMEM_ATTN = 32768 + 2 * 32768;    // 98304
    cudaFuncSetAttribute(gemm_qkv, cudaFuncAttributeMaxDynamicSharedMemorySize, SMEM_GEMM);
    cudaFuncSetAttribute(gemm_mma, cudaFuncAttributeMaxDynamicSharedMemorySize, SMEM_GEMM);
    cudaFuncSetAttribute(attn_mma, cudaFuncAttributeMaxDynamicSharedMemorySize, SMEM_ATTN);

    // 0) weight transpose+split
    splitT<<<dim3(E3 / 32, Ez / 32), dim3(32, 8)>>>(w_attn, wah, wal, Ez, E3);
    splitT<<<dim3(Ez / 32, Ez / 32), dim3(32, 8)>>>(w_proj, wph, wpl, Ez, Ez);
    // 1) split x
    split_hl<<<(Mz * Ez) / 1024, 256>>>(x, ah, al);
    // 2) past -> present + kh/kl/vh/vl [0:P)
    past_split<<<(int)((size_t)2 * Bz * Hz * Pz * Dz / 1024), 256>>>(
        past, present, kh, kl, vh, vl);
    // 3) QKV GEMM, fused routing epilogue
    gemm_qkv<<<dim3(E3 / 128, Mz / 128), 256, SMEM_GEMM>>>(
        ah, al, wah, wal, b_attn, present, qh, ql, kh, kl, vh, vl);
    // 4) attention (HMMA flash), fused hi/lo output split
    attn_mma<<<dim3(Ssz / 128, Hz, Bz), 256, SMEM_ATTN>>>(qh, ql, kh, kl, vh, vl,
                                                          ah, al);
    // 5) out = attn @ w_proj + b_proj
    gemm_mma<<<dim3(Ez / 128, Mz / 128), 256, SMEM_GEMM>>>(ah, al, wph, wpl,
                                                           b_proj, out, Ez, Ez);
}

// round 9
// speedup vs baseline: 4.9627x; 1.0503x over previous
#include <cuda_runtime.h>
#include <cuda_bf16.h>
#include <cstdint>
#include <cstddef>

#define Bz   4
#define Ssz  1024
#define Pz   1024
#define Ez   1024
#define Hz   16
#define Dz   64
#define NSz  2048
#define Mz   4096
#define E3   3072

// ---------------- scratch ---------------------------------------------------
__device__ __align__(16) __nv_bfloat16 g_ah[(size_t)Mz * Ez];
__device__ __align__(16) __nv_bfloat16 g_al[(size_t)Mz * Ez];
__device__ __align__(16) __nv_bfloat16 g_wah[(size_t)E3 * Ez];
__device__ __align__(16) __nv_bfloat16 g_wal[(size_t)E3 * Ez];
__device__ __align__(16) __nv_bfloat16 g_wph[(size_t)Ez * Ez];
__device__ __align__(16) __nv_bfloat16 g_wpl[(size_t)Ez * Ez];
__device__ __align__(16) __nv_bfloat16 g_qh[(size_t)Bz * Hz * Ssz * Dz];
__device__ __align__(16) __nv_bfloat16 g_ql[(size_t)Bz * Hz * Ssz * Dz];
__device__ __align__(16) __nv_bfloat16 g_kh[(size_t)Bz * Hz * NSz * Dz];
__device__ __align__(16) __nv_bfloat16 g_kl[(size_t)Bz * Hz * NSz * Dz];
__device__ __align__(16) __nv_bfloat16 g_vh[(size_t)Bz * Hz * NSz * Dz];
__device__ __align__(16) __nv_bfloat16 g_vl[(size_t)Bz * Hz * NSz * Dz];

// ---------------- PTX helpers ----------------------------------------------
__device__ __forceinline__ uint32_t smem_u32(const void* p) {
    uint32_t a;
    asm("{ .reg .u64 t; cvta.to.shared.u64 t, %1; cvt.u32.u64 %0, t; }"
        : "=r"(a) : "l"(p));
    return a;
}
#define CP_ASYNC16(dst, src) \
    asm volatile("cp.async.cg.shared.global [%0], [%1], 16;" \
                 :: "r"(dst), "l"(src) : "memory")
#define CP_COMMIT() asm volatile("cp.async.commit_group;" ::: "memory")
#define CP_WAIT1()  asm volatile("cp.async.wait_group 1;" ::: "memory")

#define LDSM4(r, a) \
    asm volatile("ldmatrix.sync.aligned.m8n8.x4.shared.b16 {%0,%1,%2,%3}, [%4];" \
                 : "=r"((r)[0]), "=r"((r)[1]), "=r"((r)[2]), "=r"((r)[3]) : "r"(a))
#define LDSM4T(r, a) \
    asm volatile("ldmatrix.sync.aligned.m8n8.x4.trans.shared.b16 {%0,%1,%2,%3}, [%4];" \
                 : "=r"((r)[0]), "=r"((r)[1]), "=r"((r)[2]), "=r"((r)[3]) : "r"(a))

#define MMA16816(c, a, b0, b1) \
    asm volatile("mma.sync.aligned.m16n8k16.row.col.f32.bf16.bf16.f32 " \
                 "{%0,%1,%2,%3},{%4,%5,%6,%7},{%8,%9},{%0,%1,%2,%3};" \
                 : "+f"((c)[0]), "+f"((c)[1]), "+f"((c)[2]), "+f"((c)[3]) \
                 : "r"((a)[0]), "r"((a)[1]), "r"((a)[2]), "r"((a)[3]), \
                   "r"(b0), "r"(b1))

#define SW128(o) ((o) ^ (((o) >> 3) & 0x70))

__device__ __forceinline__ void packhl(float f0, float f1, uint32_t& h, uint32_t& l) {
    __nv_bfloat16 h0 = __float2bfloat16(f0), h1 = __float2bfloat16(f1);
    __nv_bfloat16 l0 = __float2bfloat16(f0 - __bfloat162float(h0));
    __nv_bfloat16 l1 = __float2bfloat16(f1 - __bfloat162float(h1));
    __nv_bfloat162 hv(h0, h1), lv(l0, l1);
    h = *(uint32_t*)&hv;
    l = *(uint32_t*)&lv;
}

// ---------------------------------------------------------------------------
__global__ __launch_bounds__(256) void split_hl(
    const float* __restrict__ src, __nv_bfloat16* __restrict__ hi,
    __nv_bfloat16* __restrict__ lo)
{
    size_t i = (size_t)blockIdx.x * 256 + threadIdx.x;
    float4 v = ((const float4*)src)[i];
    uint32_t h0, l0, h1, l1;
    packhl(v.x, v.y, h0, l0);
    packhl(v.z, v.w, h1, l1);
    ((uint32_t*)hi)[2 * i]     = h0;
    ((uint32_t*)hi)[2 * i + 1] = h1;
    ((uint32_t*)lo)[2 * i]     = l0;
    ((uint32_t*)lo)[2 * i + 1] = l1;
}

// ---------------------------------------------------------------------------
__global__ __launch_bounds__(256) void past_split(
    const float* __restrict__ past, float* __restrict__ present,
    __nv_bfloat16* __restrict__ kh, __nv_bfloat16* __restrict__ kl,
    __nv_bfloat16* __restrict__ vh, __nv_bfloat16* __restrict__ vl)
{
    size_t i4 = (size_t)blockIdx.x * 256 + threadIdx.x;
    size_t e = i4 * 4;
    int d = (int)(e & 63);
    size_t r = e >> 6;
    int t = (int)(r % Pz); r /= Pz;
    int h = (int)(r % Hz); r /= Hz;
    int b = (int)(r % Bz);
    int c = (int)(r / Bz);
    float4 v = *(const float4*)(past + e);
    size_t pidx = ((((size_t)c * Bz + b) * Hz + h) * NSz + t) * Dz + d;
    *(float4*)(present + pidx) = v;
    uint32_t h0, l0, h1, l1;
    packhl(v.x, v.y, h0, l0);
    packhl(v.z, v.w, h1, l1);
    size_t sidx = (((size_t)(b * Hz + h)) * NSz + t) * Dz + d;
    __nv_bfloat16* hp = (c == 0) ? kh : vh;
    __nv_bfloat16* lp = (c == 0) ? kl : vl;
    *(uint32_t*)(hp + sidx)     = h0;
    *(uint32_t*)(hp + sidx + 2) = h1;
    *(uint32_t*)(lp + sidx)     = l0;
    *(uint32_t*)(lp + sidx + 2) = l1;
}

// ---------------------------------------------------------------------------
__global__ __launch_bounds__(256) void splitT(
    const float* __restrict__ src, __nv_bfloat16* __restrict__ hi,
    __nv_bfloat16* __restrict__ lo, int K, int N)
{
    __shared__ float t[32][33];
    int n0 = blockIdx.x * 32, k0 = blockIdx.y * 32;
    int tx = threadIdx.x, ty = threadIdx.y;
#pragma unroll
    for (int i = 0; i < 32; i += 8)
        t[ty + i][tx] = src[(size_t)(k0 + ty + i) * N + (n0 + tx)];
    __syncthreads();
#pragma unroll
    for (int i = 0; i < 32; i += 8) {
        int n = n0 + ty + i, k = k0 + tx;
        float v = t[tx][ty + i];
        __nv_bfloat16 h = __float2bfloat16(v);
        hi[(size_t)n * K + k] = h;
        lo[(size_t)n * K + k] = __float2bfloat16(v - __bfloat162float(h));
    }
}

// ---------------------------------------------------------------------------
// GEMM mainloop v2: BK=32, hi|lo packed in 128B rows, 3-stage pipeline.
// smem layout: stage s at s*32768; A2 at +0 (16KB), B2 at +16384.
// ---------------------------------------------------------------------------
struct GemmCore {
    float c[2][8][4];
};

__device__ __forceinline__ void gemm_mainloop(
    GemmCore& G, uint32_t sb, int tid, int wid, int lane,
    const char* gAh, const char* gAl, const char* gBh, const char* gBl,
    int Kb, int nck)
{
    const int wm = wid & 3, wn = wid >> 2;

    auto copy_stage = [&](int buf, int ck) {
        const int koff = ck * 64;                    // 32 elems * 2B
#pragma unroll
        for (int t = 0; t < 2; t++) {
            uint32_t s = sb + buf * 32768 + t * 16384;
#pragma unroll
            for (int j = 0; j < 4; j++) {
                int i = tid + 256 * j;
                int rr = i >> 3, cc = (i & 7) << 4;  // cc 0..112
                const char* g = (t == 0 ? (cc < 64 ? gAh : gAl)
                                        : (cc < 64 ? gBh : gBl))
                                + koff + (cc & 63);
                CP_ASYNC16(s + SW128(rr * 128 + cc), g + (size_t)rr * Kb);
            }
        }
    };

    copy_stage(0, 0); CP_COMMIT();
    copy_stage(1, 1); CP_COMMIT();

#pragma unroll
    for (int mf = 0; mf < 2; mf++)
#pragma unroll
        for (int nf = 0; nf < 8; nf++)
#pragma unroll
            for (int k = 0; k < 4; k++) G.c[mf][nf][k] = 0.f;

    const int lrow = lane & 15, lhalf = lane >> 4;
    int buf = 0;

    for (int ck = 0; ck < nck; ck++) {
        CP_WAIT1();
        __syncthreads();
        if (ck + 2 < nck) {
            int nb = buf + 2; if (nb >= 3) nb -= 3;
            copy_stage(nb, ck + 2);
        }
        CP_COMMIT();

        const uint32_t tA = sb + buf * 32768;
        const uint32_t tB = tA + 16384;

#pragma unroll
        for (int k16 = 0; k16 < 2; k16++) {
            const int kb = k16 * 32 + lhalf * 16;    // hi chunk byte col (<64)
            uint32_t ah[2][4], al[2][4], bh[4][4], bl[4][4];
#pragma unroll
            for (int mf = 0; mf < 2; mf++) {
                int row = wm * 32 + mf * 16 + lrow;
                LDSM4(ah[mf], tA + SW128(row * 128 + kb));
                LDSM4(al[mf], tA + SW128(row * 128 + kb + 64));
            }
#pragma unroll
            for (int bp = 0; bp < 4; bp++) {
                int row = wn * 64 + bp * 16 + lrow;
                LDSM4(bh[bp], tB + SW128(row * 128 + kb));
                LDSM4(bl[bp], tB + SW128(row * 128 + kb + 64));
            }
#pragma unroll
            for (int mf = 0; mf < 2; mf++)
#pragma unroll
                for (int nf = 0; nf < 8; nf++) {
                    const int bp = nf >> 1, od = nf & 1;
                    MMA16816(G.c[mf][nf], ah[mf], bh[bp][od], bh[bp][od + 2]);
                    MMA16816(G.c[mf][nf], al[mf], bh[bp][od], bh[bp][od + 2]);
                    MMA16816(G.c[mf][nf], ah[mf], bl[bp][od], bl[bp][od + 2]);
                }
        }
        if (++buf >= 3) buf -= 3;
    }
}

// ---------------------------------------------------------------------------
// QKV GEMM with fused routing epilogue.
// ---------------------------------------------------------------------------
__global__ __launch_bounds__(256, 2) void gemm_qkv(
    const __nv_bfloat16* __restrict__ Ah, const __nv_bfloat16* __restrict__ Al,
    const __nv_bfloat16* __restrict__ Bh, const __nv_bfloat16* __restrict__ Bl,
    const float* __restrict__ bias, float* __restrict__ present,
    __nv_bfloat16* __restrict__ qh, __nv_bfloat16* __restrict__ ql,
    __nv_bfloat16* __restrict__ kh, __nv_bfloat16* __restrict__ kl,
    __nv_bfloat16* __restrict__ vh, __nv_bfloat16* __restrict__ vl)
{
    extern __shared__ __align__(1024) char smem[];
    const uint32_t sb = smem_u32(smem);
    const int tid = threadIdx.x, wid = tid >> 5, lane = tid & 31;
    const int bn = blockIdx.x, bm = blockIdx.y;
    const int K = Ez;

    GemmCore G;
    gemm_mainloop(G, sb, tid, wid, lane,
                  (const char*)(Ah + (size_t)(bm * 128) * K),
                  (const char*)(Al + (size_t)(bm * 128) * K),
                  (const char*)(Bh + (size_t)(bn * 128) * K),
                  (const char*)(Bl + (size_t)(bn * 128) * K),
                  K * 2, K >> 5);

    const int wm = wid & 3, wn = wid >> 2;
    const int colbase = bn * 128 + wn * 64;
    const int sec = colbase >> 10;
    const int hh = (colbase & 1023) >> 6;
    const int d0 = (lane & 3) * 2;
    const int r0 = bm * 128 + wm * 32 + (lane >> 2);

#pragma unroll
    for (int mf = 0; mf < 2; mf++) {
#pragma unroll
        for (int half = 0; half < 2; half++) {
            const int r = r0 + mf * 16 + half * 8;
            const int b = r >> 10, s = r & 1023;
            const int e0 = half * 2;
#pragma unroll
            for (int nf = 0; nf < 8; nf++) {
                const int d = d0 + nf * 8;
                float vx = G.c[mf][nf][e0]     + bias[sec * 1024 + hh * 64 + d];
                float vy = G.c[mf][nf][e0 + 1] + bias[sec * 1024 + hh * 64 + d + 1];
                if (sec == 0) {
                    uint32_t ph, pl;
                    packhl(vx * 0.125f, vy * 0.125f, ph, pl);
                    size_t idx = (((size_t)(b * Hz + hh)) * Ssz + s) * Dz + d;
                    *(uint32_t*)(qh + idx) = ph;
                    *(uint32_t*)(ql + idx) = pl;
                } else {
                    size_t t = (size_t)Pz + s;
                    size_t pidx = ((((size_t)(sec - 1) * Bz + b) * Hz + hh) * NSz + t) * Dz + d;
                    float2 pv = { vx, vy };
                    *(float2*)(present + pidx) = pv;
                    uint32_t ph, pl;
                    packhl(vx, vy, ph, pl);
                    size_t sidx = (((size_t)(b * Hz + hh)) * NSz + t) * Dz + d;
                    if (sec == 1) {
                        *(uint32_t*)(kh + sidx) = ph;
                        *(uint32_t*)(kl + sidx) = pl;
                    } else {
                        *(uint32_t*)(vh + sidx) = ph;
                        *(uint32_t*)(vl + sidx) = pl;
                    }
                }
            }
        }
    }
}

// ---------------------------------------------------------------------------
// proj GEMM
// ---------------------------------------------------------------------------
__global__ __launch_bounds__(256, 2) void gemm_mma(
    const __nv_bfloat16* __restrict__ Ah, const __nv_bfloat16* __restrict__ Al,
    const __nv_bfloat16* __restrict__ Bh, const __nv_bfloat16* __restrict__ Bl,
    const float* __restrict__ bias, float* __restrict__ C, int N, int K)
{
    extern __shared__ __align__(1024) char smem[];
    const uint32_t sb = smem_u32(smem);
    const int tid = threadIdx.x, wid = tid >> 5, lane = tid & 31;
    const int bn = blockIdx.x, bm = blockIdx.y;

    GemmCore G;
    gemm_mainloop(G, sb, tid, wid, lane,
                  (const char*)(Ah + (size_t)(bm * 128) * K),
                  (const char*)(Al + (size_t)(bm * 128) * K),
                  (const char*)(Bh + (size_t)(bn * 128) * K),
                  (const char*)(Bl + (size_t)(bn * 128) * K),
                  K * 2, K >> 5);

    const int wm = wid & 3, wn = wid >> 2;
    const int crow = bm * 128 + wm * 32 + (lane >> 2);
    const int ccol = bn * 128 + wn * 64 + (lane & 3) * 2;
    const float* bp = bias + ccol;
#pragma unroll
    for (int mf = 0; mf < 2; mf++) {
#pragma unroll
        for (int nf = 0; nf < 8; nf++) {
            float2 bv = *(const float2*)(bp + nf * 8);
            float2 v0 = { G.c[mf][nf][0] + bv.x, G.c[mf][nf][1] + bv.y };
            float2 v1 = { G.c[mf][nf][2] + bv.x, G.c[mf][nf][3] + bv.y };
            size_t r0i = (size_t)(crow + mf * 16) * N + ccol + nf * 8;
            *(float2*)(C + r0i) = v0;
            *(float2*)(C + r0i + 8 * (size_t)N) = v1;
        }
    }
}

// ---------------------------------------------------------------------------
// HMMA flash attention (R8-validated; qt order reversed for load balance)
// ---------------------------------------------------------------------------
__global__ __launch_bounds__(256) void attn_mma(
    const __nv_bfloat16* __restrict__ qh_g, const __nv_bfloat16* __restrict__ ql_g,
    const __nv_bfloat16* __restrict__ kh_g, const __nv_bfloat16* __restrict__ kl_g,
    const __nv_bfloat16* __restrict__ vh_g, const __nv_bfloat16* __restrict__ vl_g,
    __nv_bfloat16* __restrict__ oh, __nv_bfloat16* __restrict__ ol)
{
    extern __shared__ __align__(1024) char smem[];
    const uint32_t sb = smem_u32(smem);
    const int tid = threadIdx.x, wid = tid >> 5, lane = tid & 31;
    const int qt = (int)gridDim.x - 1 - (int)blockIdx.x;   // longest first
    const int h = blockIdx.y, b = blockIdx.z;
    const int lrow = lane & 15, lhalf = lane >> 4;

    const size_t bh = (size_t)(b * Hz + h);
    const char* qhg = (const char*)(qh_g + (bh * Ssz + (size_t)qt * 128) * Dz);
    const char* qlg = (const char*)(ql_g + (bh * Ssz + (size_t)qt * 128) * Dz);
    const char* kvg[4] = { (const char*)(kh_g + bh * NSz * Dz),
                           (const char*)(kl_g + bh * NSz * Dz),
                           (const char*)(vh_g + bh * NSz * Dz),
                           (const char*)(vl_g + bh * NSz * Dz) };

    const int diag0 = Pz + qt * 128;
    const int ntiles = (diag0 + 128) >> 6;

    auto copy_kv = [&](int buf, int t) {
        const size_t off = (size_t)t * 64 * 128;
#pragma unroll
        for (int p = 0; p < 4; p++) {
            uint32_t s = sb + 32768 + buf * 32768 + p * 8192;
            const char* g = kvg[p] + off;
#pragma unroll
            for (int j = 0; j < 2; j++) {
                int i = tid + 256 * j;
                int r = i >> 3, c = (i & 7) << 4;
                CP_ASYNC16(s + SW128(r * 128 + c), g + r * 128 + c);
            }
        }
    };

#pragma unroll
    for (int j = 0; j < 4; j++) {
        int i = tid + 256 * j;
        int r = i >> 3, c = (i & 7) << 4;
        CP_ASYNC16(sb + SW128(r * 128 + c), qhg + r * 128 + c);
        CP_ASYNC16(sb + 16384 + SW128(r * 128 + c), qlg + r * 128 + c);
    }
    copy_kv(0, 0); CP_COMMIT();
    copy_kv(1, 1); CP_COMMIT();

    CP_WAIT1();
    __syncthreads();

    uint32_t qfh[4][4], qfl[4][4];
#pragma unroll
    for (int kk = 0; kk < 4; kk++) {
        uint32_t a = SW128((wid * 16 + lrow) * 128 + kk * 32 + lhalf * 16);
        LDSM4(qfh[kk], sb + a);
        LDSM4(qfl[kk], sb + 16384 + a);
    }

    float o[8][4];
#pragma unroll
    for (int nf = 0; nf < 8; nf++)
#pragma unroll
        for (int e = 0; e < 4; e++) o[nf][e] = 0.f;
    float m0 = -1e30f, m1 = -1e30f, l0 = 0.f, l1 = 0.f;

    const int qloc0 = wid * 16 + (lane >> 2);

    for (int it = 0; it < ntiles; it++) {
        if (it > 0) { CP_WAIT1(); __syncthreads(); }
        const int buf = it & 1;
        const int kt = it * 64;
        const uint32_t tK = sb + 32768 + buf * 32768;
        const uint32_t tV = tK + 16384;

        float s[8][4];
#pragma unroll
        for (int nf = 0; nf < 8; nf++)
#pragma unroll
            for (int e = 0; e < 4; e++) s[nf][e] = 0.f;

#pragma unroll
        for (int kk = 0; kk < 4; kk++) {
            const int kb = kk * 32 + lhalf * 16;
            uint32_t kh4[4][4], kl4[4][4];
#pragma unroll
            for (int n16 = 0; n16 < 4; n16++) {
                uint32_t a = SW128((n16 * 16 + lrow) * 128 + kb);
                LDSM4(kh4[n16], tK + a);
                LDSM4(kl4[n16], tK + 8192 + a);
            }
#pragma unroll
            for (int nf = 0; nf < 8; nf++) {
                const int n16 = nf >> 1, od = nf & 1;
                MMA16816(s[nf], qfh[kk], kh4[n16][od], kh4[n16][od + 2]);
                MMA16816(s[nf], qfl[kk], kh4[n16][od], kh4[n16][od + 2]);
                MMA16816(s[nf], qfh[kk], kl4[n16][od], kl4[n16][od + 2]);
            }
        }

        if (kt + 63 > diag0) {
            const int lim0 = diag0 - kt + qloc0;
#pragma unroll
            for (int nf = 0; nf < 8; nf++) {
                int c0 = nf * 8 + (lane & 3) * 2;
                if (c0 > lim0)     s[nf][0] = -1e30f;
                if (c0 + 1 > lim0) s[nf][1] = -1e30f;
                if (c0 > lim0 + 8)     s[nf][2] = -1e30f;
                if (c0 + 1 > lim0 + 8) s[nf][3] = -1e30f;
            }
        }

        float mx0 = -1e30f, mx1 = -1e30f;
#pragma unroll
        for (int nf = 0; nf < 8; nf++) {
            mx0 = fmaxf(mx0, fmaxf(s[nf][0], s[nf][1]));
            mx1 = fmaxf(mx1, fmaxf(s[nf][2], s[nf][3]));
        }
        mx0 = fmaxf(mx0, __shfl_xor_sync(0xffffffffu, mx0, 1));
        mx0 = fmaxf(mx0, __shfl_xor_sync(0xffffffffu, mx0, 2));
        mx1 = fmaxf(mx1, __shfl_xor_sync(0xffffffffu, mx1, 1));
        mx1 = fmaxf(mx1, __shfl_xor_sync(0xffffffffu, mx1, 2));
        const float mn0 = fmaxf(m0, mx0), mn1 = fmaxf(m1, mx1);
        const float a0 = __expf(m0 - mn0), a1 = __expf(m1 - mn1);
        m0 = mn0; m1 = mn1;
        float sm0 = 0.f, sm1 = 0.f;
#pragma unroll
        for (int nf = 0; nf < 8; nf++) {
            s[nf][0] = __expf(s[nf][0] - mn0);
            s[nf][1] = __expf(s[nf][1] - mn0);
            s[nf][2] = __expf(s[nf][2] - mn1);
            s[nf][3] = __expf(s[nf][3] - mn1);
            sm0 += s[nf][0] + s[nf][1];
            sm1 += s[nf][2] + s[nf][3];
        }
        sm0 += __shfl_xor_sync(0xffffffffu, sm0, 1);
        sm0 += __shfl_xor_sync(0xffffffffu, sm0, 2);
        sm1 += __shfl_xor_sync(0xffffffffu, sm1, 1);
        sm1 += __shfl_xor_sync(0xffffffffu, sm1, 2);
        l0 = l0 * a0 + sm0;
        l1 = l1 * a1 + sm1;
#pragma unroll
        for (int nf = 0; nf < 8; nf++) {
            o[nf][0] *= a0; o[nf][1] *= a0;
            o[nf][2] *= a1; o[nf][3] *= a1;
        }

        uint32_t ph[4][4], pl[4][4];
#pragma unroll
        for (int kk = 0; kk < 4; kk++) {
            packhl(s[2 * kk][0],     s[2 * kk][1],     ph[kk][0], pl[kk][0]);
            packhl(s[2 * kk][2],     s[2 * kk][3],     ph[kk][1], pl[kk][1]);
            packhl(s[2 * kk + 1][0], s[2 * kk + 1][1], ph[kk][2], pl[kk][2]);
            packhl(s[2 * kk + 1][2], s[2 * kk + 1][3], ph[kk][3], pl[kk][3]);
        }

#pragma unroll
        for (int kk = 0; kk < 4; kk++) {
#pragma unroll
            for (int dn = 0; dn < 4; dn++) {
                uint32_t a = SW128((kk * 16 + lrow) * 128 + dn * 32 + lhalf * 16);
                uint32_t vh4[4], vl4[4];
                LDSM4T(vh4, tV + a);
                LDSM4T(vl4, tV + 8192 + a);
#pragma unroll
                for (int od = 0; od < 2; od++) {
                    const int nf = dn * 2 + od;
                    MMA16816(o[nf], ph[kk], vh4[od * 2], vh4[od * 2 + 1]);
                    MMA16816(o[nf], pl[kk], vh4[od * 2], vh4[od * 2 + 1]);
                    MMA16816(o[nf], ph[kk], vl4[od * 2], vl4[od * 2 + 1]);
                }
            }
        }

        __syncthreads();
        if (it + 2 < ntiles) copy_kv(buf, it + 2);
        CP_COMMIT();
    }

    const float i0 = 1.f / l0, i1 = 1.f / l1;
    const int qrow = qt * 128 + qloc0;
    const size_t base0 = (size_t)(b * Ssz + qrow) * Ez + h * 64 + (lane & 3) * 2;
    const size_t base1 = base0 + 8 * (size_t)Ez;
#pragma unroll
    for (int nf = 0; nf < 8; nf++) {
        uint32_t ph0, pl0, ph1, pl1;
        packhl(o[nf][0] * i0, o[nf][1] * i0, ph0, pl0);
        packhl(o[nf][2] * i1, o[nf][3] * i1, ph1, pl1);
        *(uint32_t*)(oh + base0 + nf * 8) = ph0;
        *(uint32_t*)(ol + base0 + nf * 8) = pl0;
        *(uint32_t*)(oh + base1 + nf * 8) = ph1;
        *(uint32_t*)(ol + base1 + nf * 8) = pl1;
    }
}

// ---------------------------------------------------------------------------
extern "C" void kernel_launch(void* const* d_in, const int* in_sizes, int n_in,
                              void* d_out, int out_size)
{
    const float* x      = (const float*)d_in[0];
    const float* past   = (const float*)d_in[1];
    const float* w_attn = (const float*)d_in[2];
    const float* b_attn = (const float*)d_in[3];
    const float* w_proj = (const float*)d_in[4];
    const float* b_proj = (const float*)d_in[5];
    float* out = (float*)d_out;
    float* present = out + (size_t)Mz * Ez;

    __nv_bfloat16 *ah, *al, *wah, *wal, *wph, *wpl, *qh, *ql, *kh, *kl, *vh, *vl;
    cudaGetSymbolAddress((void**)&ah,  g_ah);
    cudaGetSymbolAddress((void**)&al,  g_al);
    cudaGetSymbolAddress((void**)&wah, g_wah);
    cudaGetSymbolAddress((void**)&wal, g_wal);
    cudaGetSymbolAddress((void**)&wph, g_wph);
    cudaGetSymbolAddress((void**)&wpl, g_wpl);
    cudaGetSymbolAddress((void**)&qh, g_qh);
    cudaGetSymbolAddress((void**)&ql, g_ql);
    cudaGetSymbolAddress((void**)&kh, g_kh);
    cudaGetSymbolAddress((void**)&kl, g_kl);
    cudaGetSymbolAddress((void**)&vh, g_vh);
    cudaGetSymbolAddress((void**)&vl, g_vl);

    static const int SMEM_GEMM = 3 * 32768;            // 98304 (3-stage)
    static const int SMEM_ATTN = 32768 + 2 * 32768;    // 98304
    cudaFuncSetAttribute(gemm_qkv, cudaFuncAttributeMaxDynamicSharedMemorySize, SMEM_GEMM);
    cudaFuncSetAttribute(gemm_mma, cudaFuncAttributeMaxDynamicSharedMemorySize, SMEM_GEMM);
    cudaFuncSetAttribute(attn_mma, cudaFuncAttributeMaxDynamicSharedMemorySize, SMEM_ATTN);

    // 0) weight transpose+split
    splitT<<<dim3(E3 / 32, Ez / 32), dim3(32, 8)>>>(w_attn, wah, wal, Ez, E3);
    splitT<<<dim3(Ez / 32, Ez / 32), dim3(32, 8)>>>(w_proj, wph, wpl, Ez, Ez);
    // 1) split x
    split_hl<<<(Mz * Ez) / 1024, 256>>>(x, ah, al);
    // 2) past -> present + kh/kl/vh/vl [0:P)
    past_split<<<(int)((size_t)2 * Bz * Hz * Pz * Dz / 1024), 256>>>(
        past, present, kh, kl, vh, vl);
    // 3) QKV GEMM, fused routing epilogue
    gemm_qkv<<<dim3(E3 / 128, Mz / 128), 256, SMEM_GEMM>>>(
        ah, al, wah, wal, b_attn, present, qh, ql, kh, kl, vh, vl);
    // 4) attention (HMMA flash)
    attn_mma<<<dim3(Ssz / 128, Hz, Bz), 256, SMEM_ATTN>>>(qh, ql, kh, kl, vh, vl,
                                                          ah, al);
    // 5) out = attn @ w_proj + b_proj
    gemm_mma<<<dim3(Ez / 128, Mz / 128), 256, SMEM_GEMM>>>(ah, al, wph, wpl,
                                                           b_proj, out, Ez, Ez);
}

// round 10
// speedup vs baseline: 6.9504x; 1.4005x over previous
#include <cuda_runtime.h>
#include <cuda_bf16.h>
#include <cuda_fp16.h>
#include <cstdint>
#include <cstddef>

#define Bz   4
#define Ssz  1024
#define Pz   1024
#define Ez   1024
#define Hz   16
#define Dz   64
#define NSz  2048
#define Mz   4096
#define E3   3072

// ---------------- scratch ---------------------------------------------------
__device__ __align__(16) __nv_bfloat16 g_ah[(size_t)Mz * Ez];
__device__ __align__(16) __nv_bfloat16 g_al[(size_t)Mz * Ez];
__device__ __align__(16) __nv_bfloat16 g_wah[(size_t)E3 * Ez];
__device__ __align__(16) __nv_bfloat16 g_wal[(size_t)E3 * Ez];
__device__ __align__(16) __nv_bfloat16 g_wph[(size_t)Ez * Ez];
__device__ __align__(16) __nv_bfloat16 g_wpl[(size_t)Ez * Ez];
__device__ __align__(16) __half g_qf[(size_t)Bz * Hz * Ssz * Dz];
__device__ __align__(16) __half g_kf[(size_t)Bz * Hz * NSz * Dz];
__device__ __align__(16) __half g_vf[(size_t)Bz * Hz * NSz * Dz];

// ---------------- PTX helpers ----------------------------------------------
__device__ __forceinline__ uint32_t smem_u32(const void* p) {
    uint32_t a;
    asm("{ .reg .u64 t; cvta.to.shared.u64 t, %1; cvt.u32.u64 %0, t; }"
        : "=r"(a) : "l"(p));
    return a;
}
#define CP_ASYNC16(dst, src) \
    asm volatile("cp.async.cg.shared.global [%0], [%1], 16;" \
                 :: "r"(dst), "l"(src) : "memory")
#define CP_COMMIT() asm volatile("cp.async.commit_group;" ::: "memory")
#define CP_WAIT1()  asm volatile("cp.async.wait_group 1;" ::: "memory")

#define LDSM4(r, a) \
    asm volatile("ldmatrix.sync.aligned.m8n8.x4.shared.b16 {%0,%1,%2,%3}, [%4];" \
                 : "=r"((r)[0]), "=r"((r)[1]), "=r"((r)[2]), "=r"((r)[3]) : "r"(a))
#define LDSM4T(r, a) \
    asm volatile("ldmatrix.sync.aligned.m8n8.x4.trans.shared.b16 {%0,%1,%2,%3}, [%4];" \
                 : "=r"((r)[0]), "=r"((r)[1]), "=r"((r)[2]), "=r"((r)[3]) : "r"(a))

#define MMA16816(c, a, b0, b1) \
    asm volatile("mma.sync.aligned.m16n8k16.row.col.f32.bf16.bf16.f32 " \
                 "{%0,%1,%2,%3},{%4,%5,%6,%7},{%8,%9},{%0,%1,%2,%3};" \
                 : "+f"((c)[0]), "+f"((c)[1]), "+f"((c)[2]), "+f"((c)[3]) \
                 : "r"((a)[0]), "r"((a)[1]), "r"((a)[2]), "r"((a)[3]), \
                   "r"(b0), "r"(b1))

#define MMAH16816(c, a, b0, b1) \
    asm volatile("mma.sync.aligned.m16n8k16.row.col.f32.f16.f16.f32 " \
                 "{%0,%1,%2,%3},{%4,%5,%6,%7},{%8,%9},{%0,%1,%2,%3};" \
                 : "+f"((c)[0]), "+f"((c)[1]), "+f"((c)[2]), "+f"((c)[3]) \
                 : "r"((a)[0]), "r"((a)[1]), "r"((a)[2]), "r"((a)[3]), \
                   "r"(b0), "r"(b1))

#define SW128(o) ((o) ^ (((o) >> 3) & 0x70))

__device__ __forceinline__ void packhl(float f0, float f1, uint32_t& h, uint32_t& l) {
    __nv_bfloat16 h0 = __float2bfloat16(f0), h1 = __float2bfloat16(f1);
    __nv_bfloat16 l0 = __float2bfloat16(f0 - __bfloat162float(h0));
    __nv_bfloat16 l1 = __float2bfloat16(f1 - __bfloat162float(h1));
    __nv_bfloat162 hv(h0, h1), lv(l0, l1);
    h = *(uint32_t*)&hv;
    l = *(uint32_t*)&lv;
}
__device__ __forceinline__ uint32_t packh16(float f0, float f1) {
    __half2 v = __floats2half2_rn(f0, f1);
    return *(uint32_t*)&v;
}

// ---------------------------------------------------------------------------
__global__ __launch_bounds__(256) void split_hl(
    const float* __restrict__ src, __nv_bfloat16* __restrict__ hi,
    __nv_bfloat16* __restrict__ lo)
{
    size_t i = (size_t)blockIdx.x * 256 + threadIdx.x;
    float4 v = ((const float4*)src)[i];
    uint32_t h0, l0, h1, l1;
    packhl(v.x, v.y, h0, l0);
    packhl(v.z, v.w, h1, l1);
    ((uint32_t*)hi)[2 * i]     = h0;
    ((uint32_t*)hi)[2 * i + 1] = h1;
    ((uint32_t*)lo)[2 * i]     = l0;
    ((uint32_t*)lo)[2 * i + 1] = l1;
}

// ---------------------------------------------------------------------------
// past -> present fp32 + fp16 kf/vf
// ---------------------------------------------------------------------------
__global__ __launch_bounds__(256) void past_split(
    const float* __restrict__ past, float* __restrict__ present,
    __half* __restrict__ kf, __half* __restrict__ vf)
{
    size_t i4 = (size_t)blockIdx.x * 256 + threadIdx.x;
    size_t e = i4 * 4;
    int d = (int)(e & 63);
    size_t r = e >> 6;
    int t = (int)(r % Pz); r /= Pz;
    int h = (int)(r % Hz); r /= Hz;
    int b = (int)(r % Bz);
    int c = (int)(r / Bz);
    float4 v = *(const float4*)(past + e);
    size_t pidx = ((((size_t)c * Bz + b) * Hz + h) * NSz + t) * Dz + d;
    *(float4*)(present + pidx) = v;
    size_t sidx = (((size_t)(b * Hz + h)) * NSz + t) * Dz + d;
    __half* fp = (c == 0) ? kf : vf;
    *(uint32_t*)(fp + sidx)     = packh16(v.x, v.y);
    *(uint32_t*)(fp + sidx + 2) = packh16(v.z, v.w);
}

// ---------------------------------------------------------------------------
__global__ __launch_bounds__(256) void splitT(
    const float* __restrict__ src, __nv_bfloat16* __restrict__ hi,
    __nv_bfloat16* __restrict__ lo, int K, int N)
{
    __shared__ float t[32][33];
    int n0 = blockIdx.x * 32, k0 = blockIdx.y * 32;
    int tx = threadIdx.x, ty = threadIdx.y;
#pragma unroll
    for (int i = 0; i < 32; i += 8)
        t[ty + i][tx] = src[(size_t)(k0 + ty + i) * N + (n0 + tx)];
    __syncthreads();
#pragma unroll
    for (int i = 0; i < 32; i += 8) {
        int n = n0 + ty + i, k = k0 + tx;
        float v = t[tx][ty + i];
        __nv_bfloat16 h = __float2bfloat16(v);
        hi[(size_t)n * K + k] = h;
        lo[(size_t)n * K + k] = __float2bfloat16(v - __bfloat162float(h));
    }
}

// ---------------------------------------------------------------------------
// GEMM mainloop (R9-validated): BK=32, hi|lo packed rows, 3-stage pipeline.
// ---------------------------------------------------------------------------
struct GemmCore {
    float c[2][8][4];
};

__device__ __forceinline__ void gemm_mainloop(
    GemmCore& G, uint32_t sb, int tid, int wid, int lane,
    const char* gAh, const char* gAl, const char* gBh, const char* gBl,
    int Kb, int nck)
{
    const int wm = wid & 3, wn = wid >> 2;

    auto copy_stage = [&](int buf, int ck) {
        const int koff = ck * 64;
#pragma unroll
        for (int t = 0; t < 2; t++) {
            uint32_t s = sb + buf * 32768 + t * 16384;
#pragma unroll
            for (int j = 0; j < 4; j++) {
                int i = tid + 256 * j;
                int rr = i >> 3, cc = (i & 7) << 4;
                const char* g = (t == 0 ? (cc < 64 ? gAh : gAl)
                                        : (cc < 64 ? gBh : gBl))
                                + koff + (cc & 63);
                CP_ASYNC16(s + SW128(rr * 128 + cc), g + (size_t)rr * Kb);
            }
        }
    };

    copy_stage(0, 0); CP_COMMIT();
    copy_stage(1, 1); CP_COMMIT();

#pragma unroll
    for (int mf = 0; mf < 2; mf++)
#pragma unroll
        for (int nf = 0; nf < 8; nf++)
#pragma unroll
            for (int k = 0; k < 4; k++) G.c[mf][nf][k] = 0.f;

    const int lrow = lane & 15, lhalf = lane >> 4;
    int buf = 0;

    for (int ck = 0; ck < nck; ck++) {
        CP_WAIT1();
        __syncthreads();
        if (ck + 2 < nck) {
            int nb = buf + 2; if (nb >= 3) nb -= 3;
            copy_stage(nb, ck + 2);
        }
        CP_COMMIT();

        const uint32_t tA = sb + buf * 32768;
        const uint32_t tB = tA + 16384;

#pragma unroll
        for (int k16 = 0; k16 < 2; k16++) {
            const int kb = k16 * 32 + lhalf * 16;
            uint32_t ah[2][4], al[2][4], bh[4][4], bl[4][4];
#pragma unroll
            for (int mf = 0; mf < 2; mf++) {
                int row = wm * 32 + mf * 16 + lrow;
                LDSM4(ah[mf], tA + SW128(row * 128 + kb));
                LDSM4(al[mf], tA + SW128(row * 128 + kb + 64));
            }
#pragma unroll
            for (int bp = 0; bp < 4; bp++) {
                int row = wn * 64 + bp * 16 + lrow;
                LDSM4(bh[bp], tB + SW128(row * 128 + kb));
                LDSM4(bl[bp], tB + SW128(row * 128 + kb + 64));
            }
#pragma unroll
            for (int mf = 0; mf < 2; mf++)
#pragma unroll
                for (int nf = 0; nf < 8; nf++) {
                    const int bp = nf >> 1, od = nf & 1;
                    MMA16816(G.c[mf][nf], ah[mf], bh[bp][od], bh[bp][od + 2]);
                    MMA16816(G.c[mf][nf], al[mf], bh[bp][od], bh[bp][od + 2]);
                    MMA16816(G.c[mf][nf], ah[mf], bl[bp][od], bl[bp][od + 2]);
                }
        }
        if (++buf >= 3) buf -= 3;
    }
}

// ---------------------------------------------------------------------------
// QKV GEMM with fused routing epilogue (q/k/v emitted as fp16).
// ---------------------------------------------------------------------------
__global__ __launch_bounds__(256, 2) void gemm_qkv(
    const __nv_bfloat16* __restrict__ Ah, const __nv_bfloat16* __restrict__ Al,
    const __nv_bfloat16* __restrict__ Bh, const __nv_bfloat16* __restrict__ Bl,
    const float* __restrict__ bias, float* __restrict__ present,
    __half* __restrict__ qf, __half* __restrict__ kf, __half* __restrict__ vf)
{
    extern __shared__ __align__(1024) char smem[];
    const uint32_t sb = smem_u32(smem);
    const int tid = threadIdx.x, wid = tid >> 5, lane = tid & 31;
    const int bn = blockIdx.x, bm = blockIdx.y;
    const int K = Ez;

    GemmCore G;
    gemm_mainloop(G, sb, tid, wid, lane,
                  (const char*)(Ah + (size_t)(bm * 128) * K),
                  (const char*)(Al + (size_t)(bm * 128) * K),
                  (const char*)(Bh + (size_t)(bn * 128) * K),
                  (const char*)(Bl + (size_t)(bn * 128) * K),
                  K * 2, K >> 5);

    const int wm = wid & 3, wn = wid >> 2;
    const int colbase = bn * 128 + wn * 64;
    const int sec = colbase >> 10;
    const int hh = (colbase & 1023) >> 6;
    const int d0 = (lane & 3) * 2;
    const int r0 = bm * 128 + wm * 32 + (lane >> 2);

#pragma unroll
    for (int mf = 0; mf < 2; mf++) {
#pragma unroll
        for (int half = 0; half < 2; half++) {
            const int r = r0 + mf * 16 + half * 8;
            const int b = r >> 10, s = r & 1023;
            const int e0 = half * 2;
#pragma unroll
            for (int nf = 0; nf < 8; nf++) {
                const int d = d0 + nf * 8;
                float vx = G.c[mf][nf][e0]     + bias[sec * 1024 + hh * 64 + d];
                float vy = G.c[mf][nf][e0 + 1] + bias[sec * 1024 + hh * 64 + d + 1];
                if (sec == 0) {
                    size_t idx = (((size_t)(b * Hz + hh)) * Ssz + s) * Dz + d;
                    *(uint32_t*)(qf + idx) = packh16(vx * 0.125f, vy * 0.125f);
                } else {
                    size_t t = (size_t)Pz + s;
                    size_t pidx = ((((size_t)(sec - 1) * Bz + b) * Hz + hh) * NSz + t) * Dz + d;
                    float2 pv = { vx, vy };
                    *(float2*)(present + pidx) = pv;
                    size_t sidx = (((size_t)(b * Hz + hh)) * NSz + t) * Dz + d;
                    __half* fp = (sec == 1) ? kf : vf;
                    *(uint32_t*)(fp + sidx) = packh16(vx, vy);
                }
            }
        }
    }
}

// ---------------------------------------------------------------------------
// proj GEMM (bf16 3-pass, fp32 out)
// ---------------------------------------------------------------------------
__global__ __launch_bounds__(256, 2) void gemm_mma(
    const __nv_bfloat16* __restrict__ Ah, const __nv_bfloat16* __restrict__ Al,
    const __nv_bfloat16* __restrict__ Bh, const __nv_bfloat16* __restrict__ Bl,
    const float* __restrict__ bias, float* __restrict__ C, int N, int K)
{
    extern __shared__ __align__(1024) char smem[];
    const uint32_t sb = smem_u32(smem);
    const int tid = threadIdx.x, wid = tid >> 5, lane = tid & 31;
    const int bn = blockIdx.x, bm = blockIdx.y;

    GemmCore G;
    gemm_mainloop(G, sb, tid, wid, lane,
                  (const char*)(Ah + (size_t)(bm * 128) * K),
                  (const char*)(Al + (size_t)(bm * 128) * K),
                  (const char*)(Bh + (size_t)(bn * 128) * K),
                  (const char*)(Bl + (size_t)(bn * 128) * K),
                  K * 2, K >> 5);

    const int wm = wid & 3, wn = wid >> 2;
    const int crow = bm * 128 + wm * 32 + (lane >> 2);
    const int ccol = bn * 128 + wn * 64 + (lane & 3) * 2;
    const float* bp = bias + ccol;
#pragma unroll
    for (int mf = 0; mf < 2; mf++) {
#pragma unroll
        for (int nf = 0; nf < 8; nf++) {
            float2 bv = *(const float2*)(bp + nf * 8);
            float2 v0 = { G.c[mf][nf][0] + bv.x, G.c[mf][nf][1] + bv.y };
            float2 v1 = { G.c[mf][nf][2] + bv.x, G.c[mf][nf][3] + bv.y };
            size_t r0i = (size_t)(crow + mf * 16) * N + ccol + nf * 8;
            *(float2*)(C + r0i) = v0;
            *(float2*)(C + r0i + 8 * (size_t)N) = v1;
        }
    }
}

// ---------------------------------------------------------------------------
// fp16 single-pass flash attention. smem: Q 16KB + 2 stages x (K 8KB + V 8KB).
// ---------------------------------------------------------------------------
__global__ __launch_bounds__(256, 2) void attn_mma(
    const __half* __restrict__ qf_g, const __half* __restrict__ kf_g,
    const __half* __restrict__ vf_g,
    __nv_bfloat16* __restrict__ oh, __nv_bfloat16* __restrict__ ol)
{
    extern __shared__ __align__(1024) char smem[];
    const uint32_t sb = smem_u32(smem);
    const int tid = threadIdx.x, wid = tid >> 5, lane = tid & 31;
    const int qt = (int)gridDim.x - 1 - (int)blockIdx.x;   // longest first
    const int h = blockIdx.y, b = blockIdx.z;
    const int lrow = lane & 15, lhalf = lane >> 4;

    const size_t bh = (size_t)(b * Hz + h);
    const char* qg = (const char*)(qf_g + (bh * Ssz + (size_t)qt * 128) * Dz);
    const char* kg = (const char*)(kf_g + bh * NSz * Dz);
    const char* vg = (const char*)(vf_g + bh * NSz * Dz);

    const int diag0 = Pz + qt * 128;
    const int ntiles = (diag0 + 128) >> 6;

    auto copy_kv = [&](int buf, int t) {
        const size_t off = (size_t)t * 64 * 128;
        uint32_t s = sb + 16384 + buf * 16384;
#pragma unroll
        for (int j = 0; j < 2; j++) {
            int i = tid + 256 * j;
            int r = i >> 3, c = (i & 7) << 4;
            CP_ASYNC16(s + SW128(r * 128 + c), kg + off + r * 128 + c);
            CP_ASYNC16(s + 8192 + SW128(r * 128 + c), vg + off + r * 128 + c);
        }
    };

#pragma unroll
    for (int j = 0; j < 4; j++) {
        int i = tid + 256 * j;
        int r = i >> 3, c = (i & 7) << 4;
        CP_ASYNC16(sb + SW128(r * 128 + c), qg + r * 128 + c);
    }
    copy_kv(0, 0); CP_COMMIT();
    copy_kv(1, 1); CP_COMMIT();

    CP_WAIT1();
    __syncthreads();

    uint32_t qf4[4][4];
#pragma unroll
    for (int kk = 0; kk < 4; kk++) {
        uint32_t a = SW128((wid * 16 + lrow) * 128 + kk * 32 + lhalf * 16);
        LDSM4(qf4[kk], sb + a);
    }

    float o[8][4];
#pragma unroll
    for (int nf = 0; nf < 8; nf++)
#pragma unroll
        for (int e = 0; e < 4; e++) o[nf][e] = 0.f;
    float m0 = -1e30f, m1 = -1e30f, l0 = 0.f, l1 = 0.f;

    const int qloc0 = wid * 16 + (lane >> 2);

    for (int it = 0; it < ntiles; it++) {
        if (it > 0) { CP_WAIT1(); __syncthreads(); }
        const int buf = it & 1;
        const int kt = it * 64;
        const uint32_t tK = sb + 16384 + buf * 16384;
        const uint32_t tV = tK + 8192;

        float s[8][4];
#pragma unroll
        for (int nf = 0; nf < 8; nf++)
#pragma unroll
            for (int e = 0; e < 4; e++) s[nf][e] = 0.f;

#pragma unroll
        for (int kk = 0; kk < 4; kk++) {
            const int kb = kk * 32 + lhalf * 16;
            uint32_t k4[4][4];
#pragma unroll
            for (int n16 = 0; n16 < 4; n16++)
                LDSM4(k4[n16], tK + SW128((n16 * 16 + lrow) * 128 + kb));
#pragma unroll
            for (int nf = 0; nf < 8; nf++) {
                const int n16 = nf >> 1, od = nf & 1;
                MMAH16816(s[nf], qf4[kk], k4[n16][od], k4[n16][od + 2]);
            }
        }

        if (kt + 63 > diag0) {
            const int lim0 = diag0 - kt + qloc0;
#pragma unroll
            for (int nf = 0; nf < 8; nf++) {
                int c0 = nf * 8 + (lane & 3) * 2;
                if (c0 > lim0)     s[nf][0] = -1e30f;
                if (c0 + 1 > lim0) s[nf][1] = -1e30f;
                if (c0 > lim0 + 8)     s[nf][2] = -1e30f;
                if (c0 + 1 > lim0 + 8) s[nf][3] = -1e30f;
            }
        }

        float mx0 = -1e30f, mx1 = -1e30f;
#pragma unroll
        for (int nf = 0; nf < 8; nf++) {
            mx0 = fmaxf(mx0, fmaxf(s[nf][0], s[nf][1]));
            mx1 = fmaxf(mx1, fmaxf(s[nf][2], s[nf][3]));
        }
        mx0 = fmaxf(mx0, __shfl_xor_sync(0xffffffffu, mx0, 1));
        mx0 = fmaxf(mx0, __shfl_xor_sync(0xffffffffu, mx0, 2));
        mx1 = fmaxf(mx1, __shfl_xor_sync(0xffffffffu, mx1, 1));
        mx1 = fmaxf(mx1, __shfl_xor_sync(0xffffffffu, mx1, 2));
        const float mn0 = fmaxf(m0, mx0), mn1 = fmaxf(m1, mx1);
        const float a0 = __expf(m0 - mn0), a1 = __expf(m1 - mn1);
        m0 = mn0; m1 = mn1;
        float sm0 = 0.f, sm1 = 0.f;
#pragma unroll
        for (int nf = 0; nf < 8; nf++) {
            s[nf][0] = __expf(s[nf][0] - mn0);
            s[nf][1] = __expf(s[nf][1] - mn0);
            s[nf][2] = __expf(s[nf][2] - mn1);
            s[nf][3] = __expf(s[nf][3] - mn1);
            sm0 += s[nf][0] + s[nf][1];
            sm1 += s[nf][2] + s[nf][3];
        }
        sm0 += __shfl_xor_sync(0xffffffffu, sm0, 1);
        sm0 += __shfl_xor_sync(0xffffffffu, sm0, 2);
        sm1 += __shfl_xor_sync(0xffffffffu, sm1, 1);
        sm1 += __shfl_xor_sync(0xffffffffu, sm1, 2);
        l0 = l0 * a0 + sm0;
        l1 = l1 * a1 + sm1;
#pragma unroll
        for (int nf = 0; nf < 8; nf++) {
            o[nf][0] *= a0; o[nf][1] *= a0;
            o[nf][2] *= a1; o[nf][3] *= a1;
        }

        uint32_t ph[4][4];
#pragma unroll
        for (int kk = 0; kk < 4; kk++) {
            ph[kk][0] = packh16(s[2 * kk][0],     s[2 * kk][1]);
            ph[kk][1] = packh16(s[2 * kk][2],     s[2 * kk][3]);
            ph[kk][2] = packh16(s[2 * kk + 1][0], s[2 * kk + 1][1]);
            ph[kk][3] = packh16(s[2 * kk + 1][2], s[2 * kk + 1][3]);
        }

#pragma unroll
        for (int kk = 0; kk < 4; kk++) {
#pragma unroll
            for (int dn = 0; dn < 4; dn++) {
                uint32_t v4[4];
                LDSM4T(v4, tV + SW128((kk * 16 + lrow) * 128 + dn * 32 + lhalf * 16));
#pragma unroll
                for (int od = 0; od < 2; od++)
                    MMAH16816(o[dn * 2 + od], ph[kk], v4[od * 2], v4[od * 2 + 1]);
            }
        }

        __syncthreads();
        if (it + 2 < ntiles) copy_kv(buf, it + 2);
        CP_COMMIT();
    }

    const float i0 = 1.f / l0, i1 = 1.f / l1;
    const int qrow = qt * 128 + qloc0;
    const size_t base0 = (size_t)(b * Ssz + qrow) * Ez + h * 64 + (lane & 3) * 2;
    const size_t base1 = base0 + 8 * (size_t)Ez;
#pragma unroll
    for (int nf = 0; nf < 8; nf++) {
        uint32_t ph0, pl0, ph1, pl1;
        packhl(o[nf][0] * i0, o[nf][1] * i0, ph0, pl0);
        packhl(o[nf][2] * i1, o[nf][3] * i1, ph1, pl1);
        *(uint32_t*)(oh + base0 + nf * 8) = ph0;
        *(uint32_t*)(ol + base0 + nf * 8) = pl0;
        *(uint32_t*)(oh + base1 + nf * 8) = ph1;
        *(uint32_t*)(ol + base1 + nf * 8) = pl1;
    }
}

// ---------------------------------------------------------------------------
extern "C" void kernel_launch(void* const* d_in, const int* in_sizes, int n_in,
                              void* d_out, int out_size)
{
    const float* x      = (const float*)d_in[0];
    const float* past   = (const float*)d_in[1];
    const float* w_attn = (const float*)d_in[2];
    const float* b_attn = (const float*)d_in[3];
    const float* w_proj = (const float*)d_in[4];
    const float* b_proj = (const float*)d_in[5];
    float* out = (float*)d_out;
    float* present = out + (size_t)Mz * Ez;

    __nv_bfloat16 *ah, *al, *wah, *wal, *wph, *wpl;
    __half *qf, *kf, *vf;
    cudaGetSymbolAddress((void**)&ah,  g_ah);
    cudaGetSymbolAddress((void**)&al,  g_al);
    cudaGetSymbolAddress((void**)&wah, g_wah);
    cudaGetSymbolAddress((void**)&wal, g_wal);
    cudaGetSymbolAddress((void**)&wph, g_wph);
    cudaGetSymbolAddress((void**)&wpl, g_wpl);
    cudaGetSymbolAddress((void**)&qf, g_qf);
    cudaGetSymbolAddress((void**)&kf, g_kf);
    cudaGetSymbolAddress((void**)&vf, g_vf);

    static const int SMEM_GEMM = 3 * 32768;        // 98304 (3-stage)
    static const int SMEM_ATTN = 16384 + 2 * 16384;// 49152
    cudaFuncSetAttribute(gemm_qkv, cudaFuncAttributeMaxDynamicSharedMemorySize, SMEM_GEMM);
    cudaFuncSetAttribute(gemm_mma, cudaFuncAttributeMaxDynamicSharedMemorySize, SMEM_GEMM);
    cudaFuncSetAttribute(attn_mma, cudaFuncAttributeMaxDynamicSharedMemorySize, SMEM_ATTN);

    // 0) weight transpose+split
    splitT<<<dim3(E3 / 32, Ez / 32), dim3(32, 8)>>>(w_attn, wah, wal, Ez, E3);
    splitT<<<dim3(Ez / 32, Ez / 32), dim3(32, 8)>>>(w_proj, wph, wpl, Ez, Ez);
    // 1) split x
    split_hl<<<(Mz * Ez) / 1024, 256>>>(x, ah, al);
    // 2) past -> present + fp16 kf/vf [0:P)
    past_split<<<(int)((size_t)2 * Bz * Hz * Pz * Dz / 1024), 256>>>(
        past, present, kf, vf);
    // 3) QKV GEMM, fused routing epilogue (fp16 q/k/v out)
    gemm_qkv<<<dim3(E3 / 128, Mz / 128), 256, SMEM_GEMM>>>(
        ah, al, wah, wal, b_attn, present, qf, kf, vf);
    // 4) attention (fp16 single-pass flash)
    attn_mma<<<dim3(Ssz / 128, Hz, Bz), 256, SMEM_ATTN>>>(qf, kf, vf, ah, al);
    // 5) out = attn @ w_proj + b_proj
    gemm_mma<<<dim3(Ez / 128, Mz / 128), 256, SMEM_GEMM>>>(ah, al, wph, wpl,
                                                           b_proj, out, Ez, Ez);
}

// round 11
// speedup vs baseline: 11.9715x; 1.7224x over previous
#include <cuda_runtime.h>
#include <cuda_bf16.h>
#include <cuda_fp16.h>
#include <cstdint>
#include <cstddef>

#define Bz   4
#define Ssz  1024
#define Pz   1024
#define Ez   1024
#define Hz   16
#define Dz   64
#define NSz  2048
#define Mz   4096
#define E3   3072

// ---------------- scratch ---------------------------------------------------
__device__ __align__(16) __half g_xf[(size_t)Mz * Ez];          // x fp16
__device__ __align__(16) __half g_af[(size_t)Mz * Ez];          // attn out fp16
__device__ __align__(16) __half g_waf[(size_t)E3 * Ez];         // w_attn^T fp16
__device__ __align__(16) __half g_wpf[(size_t)Ez * Ez];         // w_proj^T fp16
__device__ __align__(16) __half g_qf[(size_t)Bz * Hz * Ssz * Dz];
__device__ __align__(16) __half g_kf[(size_t)Bz * Hz * NSz * Dz];
__device__ __align__(16) __half g_vf[(size_t)Bz * Hz * NSz * Dz];

// ---------------- PTX helpers ----------------------------------------------
__device__ __forceinline__ uint32_t smem_u32(const void* p) {
    uint32_t a;
    asm("{ .reg .u64 t; cvta.to.shared.u64 t, %1; cvt.u32.u64 %0, t; }"
        : "=r"(a) : "l"(p));
    return a;
}
#define CP_ASYNC16(dst, src) \
    asm volatile("cp.async.cg.shared.global [%0], [%1], 16;" \
                 :: "r"(dst), "l"(src) : "memory")
#define CP_COMMIT() asm volatile("cp.async.commit_group;" ::: "memory")
#define CP_WAIT1()  asm volatile("cp.async.wait_group 1;" ::: "memory")

#define LDSM4(r, a) \
    asm volatile("ldmatrix.sync.aligned.m8n8.x4.shared.b16 {%0,%1,%2,%3}, [%4];" \
                 : "=r"((r)[0]), "=r"((r)[1]), "=r"((r)[2]), "=r"((r)[3]) : "r"(a))
#define LDSM4T(r, a) \
    asm volatile("ldmatrix.sync.aligned.m8n8.x4.trans.shared.b16 {%0,%1,%2,%3}, [%4];" \
                 : "=r"((r)[0]), "=r"((r)[1]), "=r"((r)[2]), "=r"((r)[3]) : "r"(a))

#define MMAH16816(c, a, b0, b1) \
    asm volatile("mma.sync.aligned.m16n8k16.row.col.f32.f16.f16.f32 " \
                 "{%0,%1,%2,%3},{%4,%5,%6,%7},{%8,%9},{%0,%1,%2,%3};" \
                 : "+f"((c)[0]), "+f"((c)[1]), "+f"((c)[2]), "+f"((c)[3]) \
                 : "r"((a)[0]), "r"((a)[1]), "r"((a)[2]), "r"((a)[3]), \
                   "r"(b0), "r"(b1))

#define SW128(o) ((o) ^ (((o) >> 3) & 0x70))

__device__ __forceinline__ uint32_t packh16(float f0, float f1) {
    __half2 v = __floats2half2_rn(f0, f1);
    return *(uint32_t*)&v;
}

// ---------------------------------------------------------------------------
// fp32 -> fp16 elementwise (x)
// ---------------------------------------------------------------------------
__global__ __launch_bounds__(256) void conv16(
    const float* __restrict__ src, __half* __restrict__ dst)
{
    size_t i = (size_t)blockIdx.x * 256 + threadIdx.x;
    float4 v = ((const float4*)src)[i];
    ((uint32_t*)dst)[2 * i]     = packh16(v.x, v.y);
    ((uint32_t*)dst)[2 * i + 1] = packh16(v.z, v.w);
}

// ---------------------------------------------------------------------------
// transpose + fp16: src [K,N] f32 -> dst [N,K] fp16
// ---------------------------------------------------------------------------
__global__ __launch_bounds__(256) void transT(
    const float* __restrict__ src, __half* __restrict__ dst, int K, int N)
{
    __shared__ float t[32][33];
    int n0 = blockIdx.x * 32, k0 = blockIdx.y * 32;
    int tx = threadIdx.x, ty = threadIdx.y;
#pragma unroll
    for (int i = 0; i < 32; i += 8)
        t[ty + i][tx] = src[(size_t)(k0 + ty + i) * N + (n0 + tx)];
    __syncthreads();
#pragma unroll
    for (int i = 0; i < 32; i += 8) {
        int n = n0 + ty + i, k = k0 + tx;
        dst[(size_t)n * K + k] = __float2half(t[tx][ty + i]);
    }
}

// ---------------------------------------------------------------------------
// past -> present fp32 + fp16 kf/vf
// ---------------------------------------------------------------------------
__global__ __launch_bounds__(256) void past_split(
    const float* __restrict__ past, float* __restrict__ present,
    __half* __restrict__ kf, __half* __restrict__ vf)
{
    size_t i4 = (size_t)blockIdx.x * 256 + threadIdx.x;
    size_t e = i4 * 4;
    int d = (int)(e & 63);
    size_t r = e >> 6;
    int t = (int)(r % Pz); r /= Pz;
    int h = (int)(r % Hz); r /= Hz;
    int b = (int)(r % Bz);
    int c = (int)(r / Bz);
    float4 v = *(const float4*)(past + e);
    size_t pidx = ((((size_t)c * Bz + b) * Hz + h) * NSz + t) * Dz + d;
    *(float4*)(present + pidx) = v;
    size_t sidx = (((size_t)(b * Hz + h)) * NSz + t) * Dz + d;
    __half* fp = (c == 0) ? kf : vf;
    *(uint32_t*)(fp + sidx)     = packh16(v.x, v.y);
    *(uint32_t*)(fp + sidx + 2) = packh16(v.z, v.w);
}

// ---------------------------------------------------------------------------
// fp16 single-pass GEMM mainloop: BK=64, 3-stage pipeline, 32KB/stage.
// A tile 128x64 fp16 (16KB, SW128), B tile 128x64 fp16 (16KB).
// ---------------------------------------------------------------------------
struct GemmCore {
    float c[2][8][4];
};

__device__ __forceinline__ void gemm_mainloop(
    GemmCore& G, uint32_t sb, int tid, int wid, int lane,
    const char* gA, const char* gB, int Kb, int nck)
{
    const int wm = wid & 3, wn = wid >> 2;

    auto copy_stage = [&](int buf, int ck) {
        const int koff = ck * 128;                   // 64 elems * 2B
#pragma unroll
        for (int t = 0; t < 2; t++) {
            const char* g = (t == 0 ? gA : gB) + koff;
            uint32_t s = sb + buf * 32768 + t * 16384;
#pragma unroll
            for (int j = 0; j < 4; j++) {
                int i = tid + 256 * j;
                int rr = i >> 3, cc = (i & 7) << 4;
                CP_ASYNC16(s + SW128(rr * 128 + cc), g + (size_t)rr * Kb + cc);
            }
        }
    };

    copy_stage(0, 0); CP_COMMIT();
    copy_stage(1, 1); CP_COMMIT();

#pragma unroll
    for (int mf = 0; mf < 2; mf++)
#pragma unroll
        for (int nf = 0; nf < 8; nf++)
#pragma unroll
            for (int k = 0; k < 4; k++) G.c[mf][nf][k] = 0.f;

    const int lrow = lane & 15, lhalf = lane >> 4;
    int buf = 0;

    for (int ck = 0; ck < nck; ck++) {
        CP_WAIT1();
        __syncthreads();
        if (ck + 2 < nck) {
            int nb = buf + 2; if (nb >= 3) nb -= 3;
            copy_stage(nb, ck + 2);
        }
        CP_COMMIT();

        const uint32_t tA = sb + buf * 32768;
        const uint32_t tB = tA + 16384;

#pragma unroll
        for (int k16 = 0; k16 < 4; k16++) {
            const int kb = k16 * 32 + lhalf * 16;
            uint32_t a4[2][4], b4[4][4];
#pragma unroll
            for (int mf = 0; mf < 2; mf++)
                LDSM4(a4[mf], tA + SW128((wm * 32 + mf * 16 + lrow) * 128 + kb));
#pragma unroll
            for (int bp = 0; bp < 4; bp++)
                LDSM4(b4[bp], tB + SW128((wn * 64 + bp * 16 + lrow) * 128 + kb));
#pragma unroll
            for (int mf = 0; mf < 2; mf++)
#pragma unroll
                for (int nf = 0; nf < 8; nf++) {
                    const int bp = nf >> 1, od = nf & 1;
                    MMAH16816(G.c[mf][nf], a4[mf], b4[bp][od], b4[bp][od + 2]);
                }
        }
        if (++buf >= 3) buf -= 3;
    }
}

// ---------------------------------------------------------------------------
// QKV GEMM with fused routing epilogue (q/k/v fp16 + present fp32).
// ---------------------------------------------------------------------------
__global__ __launch_bounds__(256, 2) void gemm_qkv(
    const __half* __restrict__ A, const __half* __restrict__ B,
    const float* __restrict__ bias, float* __restrict__ present,
    __half* __restrict__ qf, __half* __restrict__ kf, __half* __restrict__ vf)
{
    extern __shared__ __align__(1024) char smem[];
    const uint32_t sb = smem_u32(smem);
    const int tid = threadIdx.x, wid = tid >> 5, lane = tid & 31;
    const int bn = blockIdx.x, bm = blockIdx.y;
    const int K = Ez;

    GemmCore G;
    gemm_mainloop(G, sb, tid, wid, lane,
                  (const char*)(A + (size_t)(bm * 128) * K),
                  (const char*)(B + (size_t)(bn * 128) * K),
                  K * 2, K >> 6);

    const int wm = wid & 3, wn = wid >> 2;
    const int colbase = bn * 128 + wn * 64;
    const int sec = colbase >> 10;
    const int hh = (colbase & 1023) >> 6;
    const int d0 = (lane & 3) * 2;
    const int r0 = bm * 128 + wm * 32 + (lane >> 2);

#pragma unroll
    for (int mf = 0; mf < 2; mf++) {
#pragma unroll
        for (int half = 0; half < 2; half++) {
            const int r = r0 + mf * 16 + half * 8;
            const int b = r >> 10, s = r & 1023;
            const int e0 = half * 2;
#pragma unroll
            for (int nf = 0; nf < 8; nf++) {
                const int d = d0 + nf * 8;
                float vx = G.c[mf][nf][e0]     + bias[sec * 1024 + hh * 64 + d];
                float vy = G.c[mf][nf][e0 + 1] + bias[sec * 1024 + hh * 64 + d + 1];
                if (sec == 0) {
                    size_t idx = (((size_t)(b * Hz + hh)) * Ssz + s) * Dz + d;
                    *(uint32_t*)(qf + idx) = packh16(vx * 0.125f, vy * 0.125f);
                } else {
                    size_t t = (size_t)Pz + s;
                    size_t pidx = ((((size_t)(sec - 1) * Bz + b) * Hz + hh) * NSz + t) * Dz + d;
                    float2 pv = { vx, vy };
                    *(float2*)(present + pidx) = pv;
                    size_t sidx = (((size_t)(b * Hz + hh)) * NSz + t) * Dz + d;
                    __half* fp = (sec == 1) ? kf : vf;
                    *(uint32_t*)(fp + sidx) = packh16(vx, vy);
                }
            }
        }
    }
}

// ---------------------------------------------------------------------------
// proj GEMM: fp16 in, fp32 out + bias
// ---------------------------------------------------------------------------
__global__ __launch_bounds__(256, 2) void gemm_proj(
    const __half* __restrict__ A, const __half* __restrict__ B,
    const float* __restrict__ bias, float* __restrict__ C, int N, int K)
{
    extern __shared__ __align__(1024) char smem[];
    const uint32_t sb = smem_u32(smem);
    const int tid = threadIdx.x, wid = tid >> 5, lane = tid & 31;
    const int bn = blockIdx.x, bm = blockIdx.y;

    GemmCore G;
    gemm_mainloop(G, sb, tid, wid, lane,
                  (const char*)(A + (size_t)(bm * 128) * K),
                  (const char*)(B + (size_t)(bn * 128) * K),
                  K * 2, K >> 6);

    const int wm = wid & 3, wn = wid >> 2;
    const int crow = bm * 128 + wm * 32 + (lane >> 2);
    const int ccol = bn * 128 + wn * 64 + (lane & 3) * 2;
    const float* bp = bias + ccol;
#pragma unroll
    for (int mf = 0; mf < 2; mf++) {
#pragma unroll
        for (int nf = 0; nf < 8; nf++) {
            float2 bv = *(const float2*)(bp + nf * 8);
            float2 v0 = { G.c[mf][nf][0] + bv.x, G.c[mf][nf][1] + bv.y };
            float2 v1 = { G.c[mf][nf][2] + bv.x, G.c[mf][nf][3] + bv.y };
            size_t r0i = (size_t)(crow + mf * 16) * N + ccol + nf * 8;
            *(float2*)(C + r0i) = v0;
            *(float2*)(C + r0i + 8 * (size_t)N) = v1;
        }
    }
}

// ---------------------------------------------------------------------------
// fp16 single-pass flash attention (R10-validated), fp16 output for proj.
// ---------------------------------------------------------------------------
__global__ __launch_bounds__(256, 2) void attn_mma(
    const __half* __restrict__ qf_g, const __half* __restrict__ kf_g,
    const __half* __restrict__ vf_g, __half* __restrict__ af)
{
    extern __shared__ __align__(1024) char smem[];
    const uint32_t sb = smem_u32(smem);
    const int tid = threadIdx.x, wid = tid >> 5, lane = tid & 31;
    const int qt = (int)gridDim.x - 1 - (int)blockIdx.x;
    const int h = blockIdx.y, b = blockIdx.z;
    const int lrow = lane & 15, lhalf = lane >> 4;

    const size_t bh = (size_t)(b * Hz + h);
    const char* qg = (const char*)(qf_g + (bh * Ssz + (size_t)qt * 128) * Dz);
    const char* kg = (const char*)(kf_g + bh * NSz * Dz);
    const char* vg = (const char*)(vf_g + bh * NSz * Dz);

    const int diag0 = Pz + qt * 128;
    const int ntiles = (diag0 + 128) >> 6;

    auto copy_kv = [&](int buf, int t) {
        const size_t off = (size_t)t * 64 * 128;
        uint32_t s = sb + 16384 + buf * 16384;
#pragma unroll
        for (int j = 0; j < 2; j++) {
            int i = tid + 256 * j;
            int r = i >> 3, c = (i & 7) << 4;
            CP_ASYNC16(s + SW128(r * 128 + c), kg + off + r * 128 + c);
            CP_ASYNC16(s + 8192 + SW128(r * 128 + c), vg + off + r * 128 + c);
        }
    };

#pragma unroll
    for (int j = 0; j < 4; j++) {
        int i = tid + 256 * j;
        int r = i >> 3, c = (i & 7) << 4;
        CP_ASYNC16(sb + SW128(r * 128 + c), qg + r * 128 + c);
    }
    copy_kv(0, 0); CP_COMMIT();
    copy_kv(1, 1); CP_COMMIT();

    CP_WAIT1();
    __syncthreads();

    uint32_t qf4[4][4];
#pragma unroll
    for (int kk = 0; kk < 4; kk++) {
        uint32_t a = SW128((wid * 16 + lrow) * 128 + kk * 32 + lhalf * 16);
        LDSM4(qf4[kk], sb + a);
    }

    float o[8][4];
#pragma unroll
    for (int nf = 0; nf < 8; nf++)
#pragma unroll
        for (int e = 0; e < 4; e++) o[nf][e] = 0.f;
    float m0 = -1e30f, m1 = -1e30f, l0 = 0.f, l1 = 0.f;

    const int qloc0 = wid * 16 + (lane >> 2);

    for (int it = 0; it < ntiles; it++) {
        if (it > 0) { CP_WAIT1(); __syncthreads(); }
        const int buf = it & 1;
        const int kt = it * 64;
        const uint32_t tK = sb + 16384 + buf * 16384;
        const uint32_t tV = tK + 8192;

        float s[8][4];
#pragma unroll
        for (int nf = 0; nf < 8; nf++)
#pragma unroll
            for (int e = 0; e < 4; e++) s[nf][e] = 0.f;

#pragma unroll
        for (int kk = 0; kk < 4; kk++) {
            const int kb = kk * 32 + lhalf * 16;
            uint32_t k4[4][4];
#pragma unroll
            for (int n16 = 0; n16 < 4; n16++)
                LDSM4(k4[n16], tK + SW128((n16 * 16 + lrow) * 128 + kb));
#pragma unroll
            for (int nf = 0; nf < 8; nf++) {
                const int n16 = nf >> 1, od = nf & 1;
                MMAH16816(s[nf], qf4[kk], k4[n16][od], k4[n16][od + 2]);
            }
        }

        if (kt + 63 > diag0) {
            const int lim0 = diag0 - kt + qloc0;
#pragma unroll
            for (int nf = 0; nf < 8; nf++) {
                int c0 = nf * 8 + (lane & 3) * 2;
                if (c0 > lim0)     s[nf][0] = -1e30f;
                if (c0 + 1 > lim0) s[nf][1] = -1e30f;
                if (c0 > lim0 + 8)     s[nf][2] = -1e30f;
                if (c0 + 1 > lim0 + 8) s[nf][3] = -1e30f;
            }
        }

        float mx0 = -1e30f, mx1 = -1e30f;
#pragma unroll
        for (int nf = 0; nf < 8; nf++) {
            mx0 = fmaxf(mx0, fmaxf(s[nf][0], s[nf][1]));
            mx1 = fmaxf(mx1, fmaxf(s[nf][2], s[nf][3]));
        }
        mx0 = fmaxf(mx0, __shfl_xor_sync(0xffffffffu, mx0, 1));
        mx0 = fmaxf(mx0, __shfl_xor_sync(0xffffffffu, mx0, 2));
        mx1 = fmaxf(mx1, __shfl_xor_sync(0xffffffffu, mx1, 1));
        mx1 = fmaxf(mx1, __shfl_xor_sync(0xffffffffu, mx1, 2));
        const float mn0 = fmaxf(m0, mx0), mn1 = fmaxf(m1, mx1);
        const float a0 = __expf(m0 - mn0), a1 = __expf(m1 - mn1);
        m0 = mn0; m1 = mn1;
        float sm0 = 0.f, sm1 = 0.f;
#pragma unroll
        for (int nf = 0; nf < 8; nf++) {
            s[nf][0] = __expf(s[nf][0] - mn0);
            s[nf][1] = __expf(s[nf][1] - mn0);
            s[nf][2] = __expf(s[nf][2] - mn1);
            s[nf][3] = __expf(s[nf][3] - mn1);
            sm0 += s[nf][0] + s[nf][1];
            sm1 += s[nf][2] + s[nf][3];
        }
        sm0 += __shfl_xor_sync(0xffffffffu, sm0, 1);
        sm0 += __shfl_xor_sync(0xffffffffu, sm0, 2);
        sm1 += __shfl_xor_sync(0xffffffffu, sm1, 1);
        sm1 += __shfl_xor_sync(0xffffffffu, sm1, 2);
        l0 = l0 * a0 + sm0;
        l1 = l1 * a1 + sm1;
#pragma unroll
        for (int nf = 0; nf < 8; nf++) {
            o[nf][0] *= a0; o[nf][1] *= a0;
            o[nf][2] *= a1; o[nf][3] *= a1;
        }

        uint32_t ph[4][4];
#pragma unroll
        for (int kk = 0; kk < 4; kk++) {
            ph[kk][0] = packh16(s[2 * kk][0],     s[2 * kk][1]);
            ph[kk][1] = packh16(s[2 * kk][2],     s[2 * kk][3]);
            ph[kk][2] = packh16(s[2 * kk + 1][0], s[2 * kk + 1][1]);
            ph[kk][3] = packh16(s[2 * kk + 1][2], s[2 * kk + 1][3]);
        }

#pragma unroll
        for (int kk = 0; kk < 4; kk++) {
#pragma unroll
            for (int dn = 0; dn < 4; dn++) {
                uint32_t v4[4];
                LDSM4T(v4, tV + SW128((kk * 16 + lrow) * 128 + dn * 32 + lhalf * 16));
#pragma unroll
                for (int od = 0; od < 2; od++)
                    MMAH16816(o[dn * 2 + od], ph[kk], v4[od * 2], v4[od * 2 + 1]);
            }
        }

        __syncthreads();
        if (it + 2 < ntiles) copy_kv(buf, it + 2);
        CP_COMMIT();
    }

    const float i0 = 1.f / l0, i1 = 1.f / l1;
    const int qrow = qt * 128 + qloc0;
    const size_t base0 = (size_t)(b * Ssz + qrow) * Ez + h * 64 + (lane & 3) * 2;
    const size_t base1 = base0 + 8 * (size_t)Ez;
#pragma unroll
    for (int nf = 0; nf < 8; nf++) {
        *(uint32_t*)(af + base0 + nf * 8) = packh16(o[nf][0] * i0, o[nf][1] * i0);
        *(uint32_t*)(af + base1 + nf * 8) = packh16(o[nf][2] * i1, o[nf][3] * i1);
    }
}

// ---------------------------------------------------------------------------
extern "C" void kernel_launch(void* const* d_in, const int* in_sizes, int n_in,
                              void* d_out, int out_size)
{
    const float* x      = (const float*)d_in[0];
    const float* past   = (const float*)d_in[1];
    const float* w_attn = (const float*)d_in[2];
    const float* b_attn = (const float*)d_in[3];
    const float* w_proj = (const float*)d_in[4];
    const float* b_proj = (const float*)d_in[5];
    float* out = (float*)d_out;
    float* present = out + (size_t)Mz * Ez;

    __half *xf, *af, *waf, *wpf, *qf, *kf, *vf;
    cudaGetSymbolAddress((void**)&xf,  g_xf);
    cudaGetSymbolAddress((void**)&af,  g_af);
    cudaGetSymbolAddress((void**)&waf, g_waf);
    cudaGetSymbolAddress((void**)&wpf, g_wpf);
    cudaGetSymbolAddress((void**)&qf, g_qf);
    cudaGetSymbolAddress((void**)&kf, g_kf);
    cudaGetSymbolAddress((void**)&vf, g_vf);

    static const int SMEM_GEMM = 3 * 32768;        // 98304 (3-stage)
    static const int SMEM_ATTN = 16384 + 2 * 16384;// 49152
    cudaFuncSetAttribute(gemm_qkv,  cudaFuncAttributeMaxDynamicSharedMemorySize, SMEM_GEMM);
    cudaFuncSetAttribute(gemm_proj, cudaFuncAttributeMaxDynamicSharedMemorySize, SMEM_GEMM);
    cudaFuncSetAttribute(attn_mma,  cudaFuncAttributeMaxDynamicSharedMemorySize, SMEM_ATTN);

    // 0) weight transpose -> fp16
    transT<<<dim3(E3 / 32, Ez / 32), dim3(32, 8)>>>(w_attn, waf, Ez, E3);
    transT<<<dim3(Ez / 32, Ez / 32), dim3(32, 8)>>>(w_proj, wpf, Ez, Ez);
    // 1) x -> fp16
    conv16<<<(Mz * Ez) / 1024, 256>>>(x, xf);
    // 2) past -> present + fp16 kf/vf [0:P)
    past_split<<<(int)((size_t)2 * Bz * Hz * Pz * Dz / 1024), 256>>>(
        past, present, kf, vf);
    // 3) QKV GEMM (fp16 single-pass), fused routing epilogue
    gemm_qkv<<<dim3(E3 / 128, Mz / 128), 256, SMEM_GEMM>>>(
        xf, waf, b_attn, present, qf, kf, vf);
    // 4) attention (fp16 single-pass flash)
    attn_mma<<<dim3(Ssz / 128, Hz, Bz), 256, SMEM_ATTN>>>(qf, kf, vf, af);
    // 5) out = attn @ w_proj + b_proj (fp16 single-pass)
    gemm_proj<<<dim3(Ez / 128, Mz / 128), 256, SMEM_GEMM>>>(af, wpf,
                                                            b_proj, out, Ez, Ez);
}

// round 12
// speedup vs baseline: 12.4661x; 1.0413x over previous
#include <cuda_runtime.h>
#include <cuda_bf16.h>
#include <cuda_fp16.h>
#include <cstdint>
#include <cstddef>

#define Bz   4
#define Ssz  1024
#define Pz   1024
#define Ez   1024
#define Hz   16
#define Dz   64
#define NSz  2048
#define Mz   4096
#define E3   3072

// log2(e) folded into q scale: 0.125 * 1.4426950408889634
#define QSCALE 0.18033688011112043f

// ---------------- scratch ---------------------------------------------------
__device__ __align__(16) __half g_xf[(size_t)Mz * Ez];
__device__ __align__(16) __half g_af[(size_t)Mz * Ez];
__device__ __align__(16) __half g_waf[(size_t)E3 * Ez];
__device__ __align__(16) __half g_wpf[(size_t)Ez * Ez];
__device__ __align__(16) __half g_qf[(size_t)Bz * Hz * Ssz * Dz];
__device__ __align__(16) __half g_kf[(size_t)Bz * Hz * NSz * Dz];
__device__ __align__(16) __half g_vf[(size_t)Bz * Hz * NSz * Dz];

// ---------------- PTX helpers ----------------------------------------------
__device__ __forceinline__ uint32_t smem_u32(const void* p) {
    uint32_t a;
    asm("{ .reg .u64 t; cvta.to.shared.u64 t, %1; cvt.u32.u64 %0, t; }"
        : "=r"(a) : "l"(p));
    return a;
}
#define CP_ASYNC16(dst, src) \
    asm volatile("cp.async.cg.shared.global [%0], [%1], 16;" \
                 :: "r"(dst), "l"(src) : "memory")
#define CP_COMMIT() asm volatile("cp.async.commit_group;" ::: "memory")
#define CP_WAIT1()  asm volatile("cp.async.wait_group 1;" ::: "memory")

#define LDSM4(r, a) \
    asm volatile("ldmatrix.sync.aligned.m8n8.x4.shared.b16 {%0,%1,%2,%3}, [%4];" \
                 : "=r"((r)[0]), "=r"((r)[1]), "=r"((r)[2]), "=r"((r)[3]) : "r"(a))
#define LDSM4T(r, a) \
    asm volatile("ldmatrix.sync.aligned.m8n8.x4.trans.shared.b16 {%0,%1,%2,%3}, [%4];" \
                 : "=r"((r)[0]), "=r"((r)[1]), "=r"((r)[2]), "=r"((r)[3]) : "r"(a))

#define MMAH16816(c, a, b0, b1) \
    asm volatile("mma.sync.aligned.m16n8k16.row.col.f32.f16.f16.f32 " \
                 "{%0,%1,%2,%3},{%4,%5,%6,%7},{%8,%9},{%0,%1,%2,%3};" \
                 : "+f"((c)[0]), "+f"((c)[1]), "+f"((c)[2]), "+f"((c)[3]) \
                 : "r"((a)[0]), "r"((a)[1]), "r"((a)[2]), "r"((a)[3]), \
                   "r"(b0), "r"(b1))

#define SW128(o) ((o) ^ (((o) >> 3) & 0x70))

__device__ __forceinline__ uint32_t packh16(float f0, float f1) {
    __half2 v = __floats2half2_rn(f0, f1);
    return *(uint32_t*)&v;
}

// ---------------------------------------------------------------------------
// Merged prep kernel: block ranges dispatch 4 independent tasks.
//  [0, 3072)        transT w_attn  (bx = i%96, by = i/96)
//  [3072, 4096)     transT w_proj  (bx = i%32, by = i/32)
//  [4096, 8192)     conv16 x
//  [8192, 16384)    past_split
// ---------------------------------------------------------------------------
__device__ __forceinline__ void do_transT(
    const float* __restrict__ src, __half* __restrict__ dst,
    int K, int N, int bx, int by, int tid)
{
    __shared__ float t[32][33];
    int n0 = bx * 32, k0 = by * 32;
    int tx = tid & 31, ty = tid >> 5;
#pragma unroll
    for (int i = 0; i < 32; i += 8)
        t[ty + i][tx] = src[(size_t)(k0 + ty + i) * N + (n0 + tx)];
    __syncthreads();
#pragma unroll
    for (int i = 0; i < 32; i += 8) {
        int n = n0 + ty + i, k = k0 + tx;
        dst[(size_t)n * K + k] = __float2half(t[tx][ty + i]);
    }
}

__global__ __launch_bounds__(256) void prep_all(
    const float* __restrict__ x, const float* __restrict__ past,
    const float* __restrict__ w_attn, const float* __restrict__ w_proj,
    __half* __restrict__ xf, float* __restrict__ present,
    __half* __restrict__ waf, __half* __restrict__ wpf,
    __half* __restrict__ kf, __half* __restrict__ vf)
{
    const int blk = blockIdx.x;
    const int tid = threadIdx.x;
    if (blk < 3072) {
        do_transT(w_attn, waf, Ez, E3, blk % 96, blk / 96, tid);
    } else if (blk < 4096) {
        int i = blk - 3072;
        do_transT(w_proj, wpf, Ez, Ez, i % 32, i / 32, tid);
    } else if (blk < 8192) {
        size_t i = (size_t)(blk - 4096) * 256 + tid;
        float4 v = ((const float4*)x)[i];
        ((uint32_t*)xf)[2 * i]     = packh16(v.x, v.y);
        ((uint32_t*)xf)[2 * i + 1] = packh16(v.z, v.w);
    } else {
        size_t i4 = (size_t)(blk - 8192) * 256 + tid;
        size_t e = i4 * 4;
        int d = (int)(e & 63);
        size_t r = e >> 6;
        int t = (int)(r % Pz); r /= Pz;
        int h = (int)(r % Hz); r /= Hz;
        int b = (int)(r % Bz);
        int c = (int)(r / Bz);
        float4 v = *(const float4*)(past + e);
        size_t pidx = ((((size_t)c * Bz + b) * Hz + h) * NSz + t) * Dz + d;
        *(float4*)(present + pidx) = v;
        size_t sidx = (((size_t)(b * Hz + h)) * NSz + t) * Dz + d;
        __half* fp = (c == 0) ? kf : vf;
        *(uint32_t*)(fp + sidx)     = packh16(v.x, v.y);
        *(uint32_t*)(fp + sidx + 2) = packh16(v.z, v.w);
    }
}

// ---------------------------------------------------------------------------
// fp16 single-pass GEMM mainloop (R11-validated): BK=64, 3-stage pipeline.
// ---------------------------------------------------------------------------
struct GemmCore {
    float c[2][8][4];
};

__device__ __forceinline__ void gemm_mainloop(
    GemmCore& G, uint32_t sb, int tid, int wid, int lane,
    const char* gA, const char* gB, int Kb, int nck)
{
    const int wm = wid & 3, wn = wid >> 2;

    auto copy_stage = [&](int buf, int ck) {
        const int koff = ck * 128;
#pragma unroll
        for (int t = 0; t < 2; t++) {
            const char* g = (t == 0 ? gA : gB) + koff;
            uint32_t s = sb + buf * 32768 + t * 16384;
#pragma unroll
            for (int j = 0; j < 4; j++) {
                int i = tid + 256 * j;
                int rr = i >> 3, cc = (i & 7) << 4;
                CP_ASYNC16(s + SW128(rr * 128 + cc), g + (size_t)rr * Kb + cc);
            }
        }
    };

    copy_stage(0, 0); CP_COMMIT();
    copy_stage(1, 1); CP_COMMIT();

#pragma unroll
    for (int mf = 0; mf < 2; mf++)
#pragma unroll
        for (int nf = 0; nf < 8; nf++)
#pragma unroll
            for (int k = 0; k < 4; k++) G.c[mf][nf][k] = 0.f;

    const int lrow = lane & 15, lhalf = lane >> 4;
    int buf = 0;

    for (int ck = 0; ck < nck; ck++) {
        CP_WAIT1();
        __syncthreads();
        if (ck + 2 < nck) {
            int nb = buf + 2; if (nb >= 3) nb -= 3;
            copy_stage(nb, ck + 2);
        }
        CP_COMMIT();

        const uint32_t tA = sb + buf * 32768;
        const uint32_t tB = tA + 16384;

#pragma unroll
        for (int k16 = 0; k16 < 4; k16++) {
            const int kb = k16 * 32 + lhalf * 16;
            uint32_t a4[2][4], b4[4][4];
#pragma unroll
            for (int mf = 0; mf < 2; mf++)
                LDSM4(a4[mf], tA + SW128((wm * 32 + mf * 16 + lrow) * 128 + kb));
#pragma unroll
            for (int bp = 0; bp < 4; bp++)
                LDSM4(b4[bp], tB + SW128((wn * 64 + bp * 16 + lrow) * 128 + kb));
#pragma unroll
            for (int mf = 0; mf < 2; mf++)
#pragma unroll
                for (int nf = 0; nf < 8; nf++) {
                    const int bp = nf >> 1, od = nf & 1;
                    MMAH16816(G.c[mf][nf], a4[mf], b4[bp][od], b4[bp][od + 2]);
                }
        }
        if (++buf >= 3) buf -= 3;
    }
}

// ---------------------------------------------------------------------------
// QKV GEMM with fused routing epilogue.
// ---------------------------------------------------------------------------
__global__ __launch_bounds__(256, 2) void gemm_qkv(
    const __half* __restrict__ A, const __half* __restrict__ B,
    const float* __restrict__ bias, float* __restrict__ present,
    __half* __restrict__ qf, __half* __restrict__ kf, __half* __restrict__ vf)
{
    extern __shared__ __align__(1024) char smem[];
    const uint32_t sb = smem_u32(smem);
    const int tid = threadIdx.x, wid = tid >> 5, lane = tid & 31;
    const int bn = blockIdx.x, bm = blockIdx.y;
    const int K = Ez;

    GemmCore G;
    gemm_mainloop(G, sb, tid, wid, lane,
                  (const char*)(A + (size_t)(bm * 128) * K),
                  (const char*)(B + (size_t)(bn * 128) * K),
                  K * 2, K >> 6);

    const int wm = wid & 3, wn = wid >> 2;
    const int colbase = bn * 128 + wn * 64;
    const int sec = colbase >> 10;
    const int hh = (colbase & 1023) >> 6;
    const int d0 = (lane & 3) * 2;
    const int r0 = bm * 128 + wm * 32 + (lane >> 2);

#pragma unroll
    for (int mf = 0; mf < 2; mf++) {
#pragma unroll
        for (int half = 0; half < 2; half++) {
            const int r = r0 + mf * 16 + half * 8;
            const int b = r >> 10, s = r & 1023;
            const int e0 = half * 2;
#pragma unroll
            for (int nf = 0; nf < 8; nf++) {
                const int d = d0 + nf * 8;
                float vx = G.c[mf][nf][e0]     + bias[sec * 1024 + hh * 64 + d];
                float vy = G.c[mf][nf][e0 + 1] + bias[sec * 1024 + hh * 64 + d + 1];
                if (sec == 0) {
                    size_t idx = (((size_t)(b * Hz + hh)) * Ssz + s) * Dz + d;
                    *(uint32_t*)(qf + idx) = packh16(vx * QSCALE, vy * QSCALE);
                } else {
                    size_t t = (size_t)Pz + s;
                    size_t pidx = ((((size_t)(sec - 1) * Bz + b) * Hz + hh) * NSz + t) * Dz + d;
                    float2 pv = { vx, vy };
                    *(float2*)(present + pidx) = pv;
                    size_t sidx = (((size_t)(b * Hz + hh)) * NSz + t) * Dz + d;
                    __half* fp = (sec == 1) ? kf : vf;
                    *(uint32_t*)(fp + sidx) = packh16(vx, vy);
                }
            }
        }
    }
}

// ---------------------------------------------------------------------------
// proj GEMM: fp16 in, fp32 out + bias
// ---------------------------------------------------------------------------
__global__ __launch_bounds__(256, 2) void gemm_proj(
    const __half* __restrict__ A, const __half* __restrict__ B,
    const float* __restrict__ bias, float* __restrict__ C, int N, int K)
{
    extern __shared__ __align__(1024) char smem[];
    const uint32_t sb = smem_u32(smem);
    const int tid = threadIdx.x, wid = tid >> 5, lane = tid & 31;
    const int bn = blockIdx.x, bm = blockIdx.y;

    GemmCore G;
    gemm_mainloop(G, sb, tid, wid, lane,
                  (const char*)(A + (size_t)(bm * 128) * K),
                  (const char*)(B + (size_t)(bn * 128) * K),
                  K * 2, K >> 6);

    const int wm = wid & 3, wn = wid >> 2;
    const int crow = bm * 128 + wm * 32 + (lane >> 2);
    const int ccol = bn * 128 + wn * 64 + (lane & 3) * 2;
    const float* bp = bias + ccol;
#pragma unroll
    for (int mf = 0; mf < 2; mf++) {
#pragma unroll
        for (int nf = 0; nf < 8; nf++) {
            float2 bv = *(const float2*)(bp + nf * 8);
            float2 v0 = { G.c[mf][nf][0] + bv.x, G.c[mf][nf][1] + bv.y };
            float2 v1 = { G.c[mf][nf][2] + bv.x, G.c[mf][nf][3] + bv.y };
            size_t r0i = (size_t)(crow + mf * 16) * N + ccol + nf * 8;
            *(float2*)(C + r0i) = v0;
            *(float2*)(C + r0i + 8 * (size_t)N) = v1;
        }
    }
}

// ---------------------------------------------------------------------------
// fp16 flash attention, 3-stage KV pipeline, exp2 softmax domain.
// smem: Q 16KB + 3 stages x (K 8KB + V 8KB) = 64KB.
// ---------------------------------------------------------------------------
__global__ __launch_bounds__(256, 2) void attn_mma(
    const __half* __restrict__ qf_g, const __half* __restrict__ kf_g,
    const __half* __restrict__ vf_g, __half* __restrict__ af)
{
    extern __shared__ __align__(1024) char smem[];
    const uint32_t sb = smem_u32(smem);
    const int tid = threadIdx.x, wid = tid >> 5, lane = tid & 31;
    const int qt = (int)gridDim.x - 1 - (int)blockIdx.x;
    const int h = blockIdx.y, b = blockIdx.z;
    const int lrow = lane & 15, lhalf = lane >> 4;

    const size_t bh = (size_t)(b * Hz + h);
    const char* qg = (const char*)(qf_g + (bh * Ssz + (size_t)qt * 128) * Dz);
    const char* kg = (const char*)(kf_g + bh * NSz * Dz);
    const char* vg = (const char*)(vf_g + bh * NSz * Dz);

    const int diag0 = Pz + qt * 128;
    const int ntiles = (diag0 + 128) >> 6;

    auto copy_kv = [&](int buf, int t) {
        const size_t off = (size_t)t * 64 * 128;
        uint32_t s = sb + 16384 + buf * 16384;
#pragma unroll
        for (int j = 0; j < 2; j++) {
            int i = tid + 256 * j;
            int r = i >> 3, c = (i & 7) << 4;
            CP_ASYNC16(s + SW128(r * 128 + c), kg + off + r * 128 + c);
            CP_ASYNC16(s + 8192 + SW128(r * 128 + c), vg + off + r * 128 + c);
        }
    };

#pragma unroll
    for (int j = 0; j < 4; j++) {
        int i = tid + 256 * j;
        int r = i >> 3, c = (i & 7) << 4;
        CP_ASYNC16(sb + SW128(r * 128 + c), qg + r * 128 + c);
    }
    copy_kv(0, 0); CP_COMMIT();
    copy_kv(1, 1); CP_COMMIT();

    float o[8][4];
#pragma unroll
    for (int nf = 0; nf < 8; nf++)
#pragma unroll
        for (int e = 0; e < 4; e++) o[nf][e] = 0.f;
    float m0 = -1e30f, m1 = -1e30f, l0 = 0.f, l1 = 0.f;

    const int qloc0 = wid * 16 + (lane >> 2);

    CP_WAIT1();
    __syncthreads();

    uint32_t qf4[4][4];
#pragma unroll
    for (int kk = 0; kk < 4; kk++) {
        uint32_t a = SW128((wid * 16 + lrow) * 128 + kk * 32 + lhalf * 16);
        LDSM4(qf4[kk], sb + a);
    }
    __syncthreads();   // Q frags cached before stage-0 KV reuse races

    int buf = 0;
    for (int it = 0; it < ntiles; it++) {
        if (it > 0) { CP_WAIT1(); __syncthreads(); }
        if (it + 2 < ntiles) {
            int nb = buf + 2; if (nb >= 3) nb -= 3;
            copy_kv(nb, it + 2);
        }
        CP_COMMIT();

        const int kt = it * 64;
        const uint32_t tK = sb + 16384 + buf * 16384;
        const uint32_t tV = tK + 8192;

        float s[8][4];
#pragma unroll
        for (int nf = 0; nf < 8; nf++)
#pragma unroll
            for (int e = 0; e < 4; e++) s[nf][e] = 0.f;

#pragma unroll
        for (int kk = 0; kk < 4; kk++) {
            const int kb = kk * 32 + lhalf * 16;
            uint32_t k4[4][4];
#pragma unroll
            for (int n16 = 0; n16 < 4; n16++)
                LDSM4(k4[n16], tK + SW128((n16 * 16 + lrow) * 128 + kb));
#pragma unroll
            for (int nf = 0; nf < 8; nf++) {
                const int n16 = nf >> 1, od = nf & 1;
                MMAH16816(s[nf], qf4[kk], k4[n16][od], k4[n16][od + 2]);
            }
        }

        if (kt + 63 > diag0) {
            const int lim0 = diag0 - kt + qloc0;
#pragma unroll
            for (int nf = 0; nf < 8; nf++) {
                int c0 = nf * 8 + (lane & 3) * 2;
                if (c0 > lim0)     s[nf][0] = -1e30f;
                if (c0 + 1 > lim0) s[nf][1] = -1e30f;
                if (c0 > lim0 + 8)     s[nf][2] = -1e30f;
                if (c0 + 1 > lim0 + 8) s[nf][3] = -1e30f;
            }
        }

        float mx0 = -1e30f, mx1 = -1e30f;
#pragma unroll
        for (int nf = 0; nf < 8; nf++) {
            mx0 = fmaxf(mx0, fmaxf(s[nf][0], s[nf][1]));
            mx1 = fmaxf(mx1, fmaxf(s[nf][2], s[nf][3]));
        }
        mx0 = fmaxf(mx0, __shfl_xor_sync(0xffffffffu, mx0, 1));
        mx0 = fmaxf(mx0, __shfl_xor_sync(0xffffffffu, mx0, 2));
        mx1 = fmaxf(mx1, __shfl_xor_sync(0xffffffffu, mx1, 1));
        mx1 = fmaxf(mx1, __shfl_xor_sync(0xffffffffu, mx1, 2));
        const float mn0 = fmaxf(m0, mx0), mn1 = fmaxf(m1, mx1);
        const float a0 = exp2f(m0 - mn0), a1 = exp2f(m1 - mn1);
        m0 = mn0; m1 = mn1;
        float sm0 = 0.f, sm1 = 0.f;
#pragma unroll
        for (int nf = 0; nf < 8; nf++) {
            s[nf][0] = exp2f(s[nf][0] - mn0);
            s[nf][1] = exp2f(s[nf][1] - mn0);
            s[nf][2] = exp2f(s[nf][2] - mn1);
            s[nf][3] = exp2f(s[nf][3] - mn1);
            sm0 += s[nf][0] + s[nf][1];
            sm1 += s[nf][2] + s[nf][3];
        }
        sm0 += __shfl_xor_sync(0xffffffffu, sm0, 1);
        sm0 += __shfl_xor_sync(0xffffffffu, sm0, 2);
        sm1 += __shfl_xor_sync(0xffffffffu, sm1, 1);
        sm1 += __shfl_xor_sync(0xffffffffu, sm1, 2);
        l0 = l0 * a0 + sm0;
        l1 = l1 * a1 + sm1;
#pragma unroll
        for (int nf = 0; nf < 8; nf++) {
            o[nf][0] *= a0; o[nf][1] *= a0;
            o[nf][2] *= a1; o[nf][3] *= a1;
        }

        uint32_t ph[4][4];
#pragma unroll
        for (int kk = 0; kk < 4; kk++) {
            ph[kk][0] = packh16(s[2 * kk][0],     s[2 * kk][1]);
            ph[kk][1] = packh16(s[2 * kk][2],     s[2 * kk][3]);
            ph[kk][2] = packh16(s[2 * kk + 1][0], s[2 * kk + 1][1]);
            ph[kk][3] = packh16(s[2 * kk + 1][2], s[2 * kk + 1][3]);
        }

#pragma unroll
        for (int kk = 0; kk < 4; kk++) {
#pragma unroll
            for (int dn = 0; dn < 4; dn++) {
                uint32_t v4[4];
                LDSM4T(v4, tV + SW128((kk * 16 + lrow) * 128 + dn * 32 + lhalf * 16));
#pragma unroll
                for (int od = 0; od < 2; od++)
                    MMAH16816(o[dn * 2 + od], ph[kk], v4[od * 2], v4[od * 2 + 1]);
            }
        }

        if (++buf >= 3) buf -= 3;
    }

    const float i0 = 1.f / l0, i1 = 1.f / l1;
    const int qrow = qt * 128 + qloc0;
    const size_t base0 = (size_t)(b * Ssz + qrow) * Ez + h * 64 + (lane & 3) * 2;
    const size_t base1 = base0 + 8 * (size_t)Ez;
#pragma unroll
    for (int nf = 0; nf < 8; nf++) {
        *(uint32_t*)(af + base0 + nf * 8) = packh16(o[nf][0] * i0, o[nf][1] * i0);
        *(uint32_t*)(af + base1 + nf * 8) = packh16(o[nf][2] * i1, o[nf][3] * i1);
    }
}

// ---------------------------------------------------------------------------
extern "C" void kernel_launch(void* const* d_in, const int* in_sizes, int n_in,
                              void* d_out, int out_size)
{
    const float* x      = (const float*)d_in[0];
    const float* past   = (const float*)d_in[1];
    const float* w_attn = (const float*)d_in[2];
    const float* b_attn = (const float*)d_in[3];
    const float* w_proj = (const float*)d_in[4];
    const float* b_proj = (const float*)d_in[5];
    float* out = (float*)d_out;
    float* present = out + (size_t)Mz * Ez;

    __half *xf, *af, *waf, *wpf, *qf, *kf, *vf;
    cudaGetSymbolAddress((void**)&xf,  g_xf);
    cudaGetSymbolAddress((void**)&af,  g_af);
    cudaGetSymbolAddress((void**)&waf, g_waf);
    cudaGetSymbolAddress((void**)&wpf, g_wpf);
    cudaGetSymbolAddress((void**)&qf, g_qf);
    cudaGetSymbolAddress((void**)&kf, g_kf);
    cudaGetSymbolAddress((void**)&vf, g_vf);

    static const int SMEM_GEMM = 3 * 32768;            // 98304
    static const int SMEM_ATTN = 16384 + 3 * 16384;    // 65536
    cudaFuncSetAttribute(gemm_qkv,  cudaFuncAttributeMaxDynamicSharedMemorySize, SMEM_GEMM);
    cudaFuncSetAttribute(gemm_proj, cudaFuncAttributeMaxDynamicSharedMemorySize, SMEM_GEMM);
    cudaFuncSetAttribute(attn_mma,  cudaFuncAttributeMaxDynamicSharedMemorySize, SMEM_ATTN);

    // 1) merged prep: weights transpose->fp16, x->fp16, past->present+kf/vf
    prep_all<<<16384, 256>>>(x, past, w_attn, w_proj,
                             xf, present, waf, wpf, kf, vf);
    // 2) QKV GEMM (fp16), fused routing epilogue
    gemm_qkv<<<dim3(E3 / 128, Mz / 128), 256, SMEM_GEMM>>>(
        xf, waf, b_attn, present, qf, kf, vf);
    // 3) attention (fp16 flash, 3-stage pipeline)
    attn_mma<<<dim3(Ssz / 128, Hz, Bz), 256, SMEM_ATTN>>>(qf, kf, vf, af);
    // 4) out = attn @ w_proj + b_proj
    gemm_proj<<<dim3(Ez / 128, Mz / 128), 256, SMEM_GEMM>>>(af, wpf,
                                                            b_proj, out, Ez, Ez);
}